// round 1
// baseline (speedup 1.0000x reference)
#include <cuda_runtime.h>
#include <math.h>

#define S_LEN 2048
#define HID   4096
#define NH    32
#define NKV   8
#define HD    128

// ---------------- scratch (static device globals; no allocations) -----------
__device__ float g_Q [S_LEN * NH  * HD];   // 32 MB
__device__ float g_K [S_LEN * NKV * HD];   //  8 MB
__device__ float g_V [S_LEN * NKV * HD];   //  8 MB
__device__ float g_AO[S_LEN * NH  * HD];   // 32 MB

// ---------------- SGEMM NT: C[M,N] = A[M,K] * B[N,K]^T ---------------------
// BM=BN=128, BK=16, 256 threads, 8x8 microtile.
#define BM 128
#define BN 128
#define BK 16
#define APAD 132   // 128 + 4 floats per shared row (33 float4) -> conflict-free reads

__global__ __launch_bounds__(256, 2)
void sgemm_nt(const float* __restrict__ A, const float* __restrict__ B,
              float* __restrict__ C, int M, int N, int K) {
    __shared__ float As[BK][APAD];
    __shared__ float Bs[BK][APAD];
    const int tid = threadIdx.x;
    const int tm = tid >> 4;          // 0..15, owns rows tm*8 .. tm*8+7
    const int tn = tid & 15;          // 0..15, owns cols tn*4..+3 and tn*4+64..+67
    const int r0 = blockIdx.y * BM;
    const int c0 = blockIdx.x * BN;

    float acc[8][8];
#pragma unroll
    for (int i = 0; i < 8; i++)
#pragma unroll
        for (int j = 0; j < 8; j++) acc[i][j] = 0.f;

    const int lrow = tid >> 2;        // 0..63 (two passes cover 128 rows)
    const int lc4  = tid & 3;         // float4 column within BK

    for (int kt = 0; kt < K; kt += BK) {
#pragma unroll
        for (int it = 0; it < 2; it++) {
            int row = lrow + it * 64;
            float4 va = *(const float4*)&A[(size_t)(r0 + row) * K + kt + lc4 * 4];
            As[lc4*4+0][row] = va.x; As[lc4*4+1][row] = va.y;
            As[lc4*4+2][row] = va.z; As[lc4*4+3][row] = va.w;
            float4 vb = *(const float4*)&B[(size_t)(c0 + row) * K + kt + lc4 * 4];
            Bs[lc4*4+0][row] = vb.x; Bs[lc4*4+1][row] = vb.y;
            Bs[lc4*4+2][row] = vb.z; Bs[lc4*4+3][row] = vb.w;
        }
        __syncthreads();
#pragma unroll
        for (int k = 0; k < BK; k++) {
            float a[8], b[8];
            float4 t;
            t = *(const float4*)&As[k][tm * 8];     a[0]=t.x; a[1]=t.y; a[2]=t.z; a[3]=t.w;
            t = *(const float4*)&As[k][tm * 8 + 4]; a[4]=t.x; a[5]=t.y; a[6]=t.z; a[7]=t.w;
            t = *(const float4*)&Bs[k][tn * 4];      b[0]=t.x; b[1]=t.y; b[2]=t.z; b[3]=t.w;
            t = *(const float4*)&Bs[k][tn * 4 + 64]; b[4]=t.x; b[5]=t.y; b[6]=t.z; b[7]=t.w;
#pragma unroll
            for (int i = 0; i < 8; i++)
#pragma unroll
                for (int j = 0; j < 8; j++) acc[i][j] += a[i] * b[j];
        }
        __syncthreads();
    }
#pragma unroll
    for (int i = 0; i < 8; i++) {
        int r = r0 + tm * 8 + i;
        float4 v0 = make_float4(acc[i][0], acc[i][1], acc[i][2], acc[i][3]);
        float4 v1 = make_float4(acc[i][4], acc[i][5], acc[i][6], acc[i][7]);
        *(float4*)&C[(size_t)r * N + c0 + tn * 4]      = v0;
        *(float4*)&C[(size_t)r * N + c0 + tn * 4 + 64] = v1;
    }
}

// ---------------- RoPE -----------------------------------------------------
__global__ void rope_kernel(float* __restrict__ X, const float* __restrict__ cosb,
                            const float* __restrict__ sinb, int nheads) {
    int idx = blockIdx.x * blockDim.x + threadIdx.x;
    int total = S_LEN * nheads * 64;
    if (idx >= total) return;
    int d = idx & 63;
    int h = (idx >> 6) % nheads;
    int s = idx / (64 * nheads);
    float c1 = cosb[s * HD + d],      s1 = sinb[s * HD + d];
    float c2 = cosb[s * HD + d + 64], s2 = sinb[s * HD + d + 64];
    float* p = X + (size_t)s * nheads * HD + h * HD;
    float x1 = p[d], x2 = p[d + 64];
    p[d]      = x1 * c1 - x2 * s1;   // q*cos + rotate_half(q)*sin, first half
    p[d + 64] = x2 * c2 + x1 * s2;   // second half
}

// ---------------- Flash attention (fp32, causal, GQA 4:1) ------------------
#define FBM 64
#define FBN 64
#define FLD 132   // row stride (floats) for Qs/Ks/Vs (33 float4)
#define PLD 68    // row stride for Ps (17 float4)
#define FLASH_SMEM ((3 * 64 * FLD + 64 * PLD + 192) * 4)

__global__ __launch_bounds__(256, 1)
void flash_attn(const float* __restrict__ Q, const float* __restrict__ Kb,
                const float* __restrict__ Vb, float* __restrict__ O) {
    extern __shared__ float sm[];
    float* Qs   = sm;                  // [64][FLD] row-major (m, d)
    float* Ks   = Qs + 64 * FLD;       // [64][FLD] (n, d)
    float* Vs   = Ks + 64 * FLD;       // [64][FLD] (n, d)
    float* Ps   = Vs + 64 * FLD;       // [64][PLD] (n, m)  — transposed scores
    float* mrow = Ps + 64 * PLD;       // [64]
    float* lrow = mrow + 64;           // [64]
    float* arow = lrow + 64;           // [64]

    const int tid = threadIdx.x;
    const int qb = blockIdx.x, h = blockIdx.y;
    const int kv = h >> 2;             // GQA: 4 query heads per kv head
    const int q0 = qb * FBM;

    // load Q tile (coalesced, conflict-free stores)
    {
        int m  = tid >> 5;
        int d4 = tid & 31;
#pragma unroll
        for (int it = 0; it < 8; it++) {
            int mm = m + it * 8;
            *(float4*)&Qs[mm * FLD + d4 * 4] =
                *(const float4*)&Q[(size_t)(q0 + mm) * (NH * HD) + h * HD + d4 * 4];
        }
    }
    if (tid < 64) { mrow[tid] = -1e30f; lrow[tid] = 0.f; }

    float oacc[4][8];
#pragma unroll
    for (int i = 0; i < 4; i++)
#pragma unroll
        for (int j = 0; j < 8; j++) oacc[i][j] = 0.f;

    const int tmS = tid >> 4, tnS = tid & 15;       // S phase: rows tmS*4+i, cols tnS+16j
    const int trow = tid >> 4, tcol = tid & 15;     // O phase: rows trow*4+i, col blocks {4tcol, 4tcol+64}
    const float scale = 0.08838834764831845f;       // 1/sqrt(128)

    for (int jb = 0; jb <= qb; jb++) {
        const int k0 = jb * FBN;
        __syncthreads();   // protect Ks/Vs/Ps against previous iteration's readers
        {
            int n  = tid >> 5;
            int d4 = tid & 31;
#pragma unroll
            for (int it = 0; it < 8; it++) {
                int nn = n + it * 8;
                size_t gi = (size_t)(k0 + nn) * (NKV * HD) + kv * HD + d4 * 4;
                *(float4*)&Ks[nn * FLD + d4 * 4] = *(const float4*)&Kb[gi];
                *(float4*)&Vs[nn * FLD + d4 * 4] = *(const float4*)&Vb[gi];
            }
        }
        __syncthreads();

        // ---- S = Q K^T (64x64x128) ----
        float sacc[4][4];
#pragma unroll
        for (int i = 0; i < 4; i++)
#pragma unroll
            for (int j = 0; j < 4; j++) sacc[i][j] = 0.f;

#pragma unroll 4
        for (int d4 = 0; d4 < 32; d4++) {
            float4 a[4], b[4];
#pragma unroll
            for (int i = 0; i < 4; i++)
                a[i] = *(const float4*)&Qs[(tmS * 4 + i) * FLD + d4 * 4];
#pragma unroll
            for (int j = 0; j < 4; j++)
                b[j] = *(const float4*)&Ks[(tnS + 16 * j) * FLD + d4 * 4];
#pragma unroll
            for (int i = 0; i < 4; i++)
#pragma unroll
                for (int j = 0; j < 4; j++)
                    sacc[i][j] += a[i].x * b[j].x + a[i].y * b[j].y +
                                  a[i].z * b[j].z + a[i].w * b[j].w;
        }
        const bool diag = (jb == qb);
#pragma unroll
        for (int i = 0; i < 4; i++) {
            int gr = q0 + tmS * 4 + i;
#pragma unroll
            for (int j = 0; j < 4; j++) {
                int gc = k0 + tnS + 16 * j;
                float sv = sacc[i][j] * scale;
                if (diag && gc > gr) sv = -1e30f;   // causal mask (exact: exp underflows to 0)
                Ps[(tnS + 16 * j) * PLD + (tmS * 4 + i)] = sv;
            }
        }
        __syncthreads();

        // ---- online softmax update ----
        {
            int r = tid >> 2, part = tid & 3;
            float lm = -1e30f;
#pragma unroll
            for (int nn = 0; nn < 16; nn++)
                lm = fmaxf(lm, Ps[(part * 16 + nn) * PLD + r]);
            lm = fmaxf(lm, __shfl_xor_sync(0xffffffffu, lm, 1));
            lm = fmaxf(lm, __shfl_xor_sync(0xffffffffu, lm, 2));
            float mprev = mrow[r];
            float mnew  = fmaxf(mprev, lm);
            float psum = 0.f;
#pragma unroll
            for (int nn = 0; nn < 16; nn++) {
                int off = (part * 16 + nn) * PLD + r;
                float p = expf(Ps[off] - mnew);
                Ps[off] = p;
                psum += p;
            }
            psum += __shfl_xor_sync(0xffffffffu, psum, 1);
            psum += __shfl_xor_sync(0xffffffffu, psum, 2);
            if (part == 0) {
                float alpha = expf(mprev - mnew);
                arow[r] = alpha;
                mrow[r] = mnew;
                lrow[r] = lrow[r] * alpha + psum;
            }
        }
        __syncthreads();

        // ---- O = alpha*O + P V (64x128x64) ----
        {
#pragma unroll
            for (int i = 0; i < 4; i++) {
                float al = arow[trow * 4 + i];
#pragma unroll
                for (int j = 0; j < 8; j++) oacc[i][j] *= al;
            }
#pragma unroll 2
            for (int n = 0; n < 64; n++) {
                float4 p4 = *(const float4*)&Ps[n * PLD + trow * 4];
                float4 va = *(const float4*)&Vs[n * FLD + tcol * 4];
                float4 vb = *(const float4*)&Vs[n * FLD + tcol * 4 + 64];
                float pp[4] = {p4.x, p4.y, p4.z, p4.w};
                float vv[8] = {va.x, va.y, va.z, va.w, vb.x, vb.y, vb.z, vb.w};
#pragma unroll
                for (int i = 0; i < 4; i++)
#pragma unroll
                    for (int j = 0; j < 8; j++) oacc[i][j] += pp[i] * vv[j];
            }
        }
    }
    __syncthreads();

    // ---- normalize + write ----
    {
#pragma unroll
        for (int i = 0; i < 4; i++) {
            int gr = q0 + trow * 4 + i;
            float inv = 1.f / lrow[trow * 4 + i];
            float4 v0 = make_float4(oacc[i][0] * inv, oacc[i][1] * inv,
                                    oacc[i][2] * inv, oacc[i][3] * inv);
            float4 v1 = make_float4(oacc[i][4] * inv, oacc[i][5] * inv,
                                    oacc[i][6] * inv, oacc[i][7] * inv);
            *(float4*)&O[(size_t)gr * (NH * HD) + h * HD + tcol * 4]      = v0;
            *(float4*)&O[(size_t)gr * (NH * HD) + h * HD + tcol * 4 + 64] = v1;
        }
    }
}

// ---------------- launch ----------------------------------------------------
extern "C" void kernel_launch(void* const* d_in, const int* in_sizes, int n_in,
                              void* d_out, int out_size) {
    const float* hs   = (const float*)d_in[0];   // hidden_states [1,2048,4096]
    const float* cosb = (const float*)d_in[1];   // cos [1,2048,128]
    const float* sinb = (const float*)d_in[2];   // sin [1,2048,128]
    // d_in[3] = attention_mask: implicit causal, unused (bit-equivalent, see notes)
    const float* Wq   = (const float*)d_in[4];   // [4096,4096]
    const float* Wk   = (const float*)d_in[5];   // [1024,4096]
    const float* Wv   = (const float*)d_in[6];   // [1024,4096]
    const float* Wo   = (const float*)d_in[7];   // [4096,4096]
    float* out = (float*)d_out;                  // [1,2048,4096] fp32

    float *Qp, *Kp, *Vp, *AOp;
    cudaGetSymbolAddress((void**)&Qp,  g_Q);
    cudaGetSymbolAddress((void**)&Kp,  g_K);
    cudaGetSymbolAddress((void**)&Vp,  g_V);
    cudaGetSymbolAddress((void**)&AOp, g_AO);

    // projections
    sgemm_nt<<<dim3(HID / BN,        S_LEN / BM), 256>>>(hs, Wq, Qp, S_LEN, NH  * HD, HID);
    sgemm_nt<<<dim3(NKV * HD / BN,   S_LEN / BM), 256>>>(hs, Wk, Kp, S_LEN, NKV * HD, HID);
    sgemm_nt<<<dim3(NKV * HD / BN,   S_LEN / BM), 256>>>(hs, Wv, Vp, S_LEN, NKV * HD, HID);

    // RoPE
    rope_kernel<<<(S_LEN * NH  * 64 + 255) / 256, 256>>>(Qp, cosb, sinb, NH);
    rope_kernel<<<(S_LEN * NKV * 64 + 255) / 256, 256>>>(Kp, cosb, sinb, NKV);

    // attention
    cudaFuncSetAttribute(flash_attn, cudaFuncAttributeMaxDynamicSharedMemorySize, FLASH_SMEM);
    flash_attn<<<dim3(S_LEN / FBM, NH), 256, FLASH_SMEM>>>(Qp, Kp, Vp, AOp);

    // output projection
    sgemm_nt<<<dim3(HID / BN, S_LEN / BM), 256>>>(AOp, Wo, out, S_LEN, NH * HD, HID);
}

// round 3
// speedup vs baseline: 1.8787x; 1.8787x over previous
#include <cuda_runtime.h>
#include <cuda_bf16.h>
#include <math.h>
#include <cstdint>

#define S_LEN 2048
#define HID   4096
#define NH    32
#define NKV   8
#define HD    128

// ---------------- scratch (static device globals; no allocations) -----------
__device__ float g_Q [S_LEN * NH  * HD];
__device__ float g_K [S_LEN * NKV * HD];
__device__ float g_V [S_LEN * NKV * HD];
__device__ float g_AO[S_LEN * NH  * HD];

// split bf16 hi/lo scratch
__device__ __nv_bfloat16 g_hs_hi[S_LEN * HID],      g_hs_lo[S_LEN * HID];
__device__ __nv_bfloat16 g_wq_hi[HID * HID],        g_wq_lo[HID * HID];
__device__ __nv_bfloat16 g_wk_hi[NKV * HD * HID],   g_wk_lo[NKV * HD * HID];
__device__ __nv_bfloat16 g_wv_hi[NKV * HD * HID],   g_wv_lo[NKV * HD * HID];
__device__ __nv_bfloat16 g_wo_hi[HID * HID],        g_wo_lo[HID * HID];
__device__ __nv_bfloat16 g_ao_hi[S_LEN * HID],      g_ao_lo[S_LEN * HID];

// ---------------- split: fp32 -> (hi, lo) bf16 ------------------------------
__global__ void split_f32(const float4* __restrict__ x,
                          uint2* __restrict__ hi, uint2* __restrict__ lo, int n4) {
    int i = blockIdx.x * blockDim.x + threadIdx.x;
    if (i >= n4) return;
    float4 v = x[i];
    float xs[4] = {v.x, v.y, v.z, v.w};
    unsigned short h[4], l[4];
#pragma unroll
    for (int j = 0; j < 4; j++) {
        __nv_bfloat16 hb = __float2bfloat16_rn(xs[j]);
        float r = xs[j] - __bfloat162float(hb);
        h[j] = __bfloat16_as_ushort(hb);
        l[j] = __bfloat16_as_ushort(__float2bfloat16_rn(r));
    }
    hi[i] = make_uint2(((uint32_t)h[1] << 16) | h[0], ((uint32_t)h[3] << 16) | h[2]);
    lo[i] = make_uint2(((uint32_t)l[1] << 16) | l[0], ((uint32_t)l[3] << 16) | l[2]);
}

// =================== HMMA split-bf16 GEMM: C = A * B^T ======================
// A_hi/lo [M,K] bf16, B_hi/lo [N,K] bf16 (K-major). C [M,N] fp32.
// Tile 128x128, BK=32, 8 warps (2m x 4n), warp tile 64x32, m16n8k16.
#define GBK 32
#define TILE_BYTES 8192              // 128 rows x 64 B
#define STAGE_BYTES (4 * TILE_BYTES) // Ahi, Alo, Bhi, Blo
#define GEMM_SMEM (2 * STAGE_BYTES)  // 64 KB, double buffered

// swizzled byte offset within a tile: row in [0,128), kc = 16B chunk in [0,4)
__device__ __forceinline__ uint32_t swoff(int row, int kc) {
    return (uint32_t)(row * 64 + ((kc ^ ((row >> 1) & 3)) << 4));
}
__device__ __forceinline__ uint32_t smem_u32(const void* p) {
    uint32_t a;
    asm("{ .reg .u64 t; cvta.to.shared.u64 t, %1; cvt.u32.u64 %0, t; }" : "=r"(a) : "l"(p));
    return a;
}
__device__ __forceinline__ void cp16(uint32_t dst, const void* src) {
    asm volatile("cp.async.cg.shared.global [%0], [%1], 16;" :: "r"(dst), "l"(src) : "memory");
}
#define CP_COMMIT() asm volatile("cp.async.commit_group;" ::: "memory")
template <int N> __device__ __forceinline__ void cp_wait() {
    asm volatile("cp.async.wait_group %0;" :: "n"(N) : "memory");
}
__device__ __forceinline__ void ldmx4(uint32_t* r, uint32_t addr) {
    asm volatile("ldmatrix.sync.aligned.m8n8.x4.shared.b16 {%0,%1,%2,%3}, [%4];"
                 : "=r"(r[0]), "=r"(r[1]), "=r"(r[2]), "=r"(r[3]) : "r"(addr));
}
__device__ __forceinline__ void mma16816(float* d, const uint32_t* a, uint32_t b0, uint32_t b1) {
    asm volatile(
        "mma.sync.aligned.m16n8k16.row.col.f32.bf16.bf16.f32 "
        "{%0,%1,%2,%3}, {%4,%5,%6,%7}, {%8,%9}, {%0,%1,%2,%3};"
        : "+f"(d[0]), "+f"(d[1]), "+f"(d[2]), "+f"(d[3])
        : "r"(a[0]), "r"(a[1]), "r"(a[2]), "r"(a[3]), "r"(b0), "r"(b1));
}

__global__ __launch_bounds__(256, 1)
void gemm_hmma(const __nv_bfloat16* __restrict__ Ahi, const __nv_bfloat16* __restrict__ Alo,
               const __nv_bfloat16* __restrict__ Bhi, const __nv_bfloat16* __restrict__ Blo,
               float* __restrict__ C, int M, int N, int K) {
    extern __shared__ char sm[];
    const uint32_t sb = smem_u32(sm);
    const int tid = threadIdx.x;
    const int wid = tid >> 5, lane = tid & 31;
    const int wm = wid >> 2, wn = wid & 3;
    const int r0 = blockIdx.y * 128;
    const int c0 = blockIdx.x * 128;
    const int NC = K / GBK;

    const __nv_bfloat16* gsrc[4] = {
        Ahi + (size_t)r0 * K, Alo + (size_t)r0 * K,
        Bhi + (size_t)c0 * K, Blo + (size_t)c0 * K };

    // prefetch one chunk into stage s
    auto prefetch = [&](int c, int s) {
        uint32_t sbase = sb + s * STAGE_BYTES;
#pragma unroll
        for (int t = 0; t < 4; t++) {
#pragma unroll
            for (int it = 0; it < 2; it++) {
                int u = tid + it * 256;        // 0..511
                int row = u >> 2, kc = u & 3;
                cp16(sbase + t * TILE_BYTES + swoff(row, kc),
                     gsrc[t] + (size_t)row * K + c * GBK + kc * 8);
            }
        }
        CP_COMMIT();
    };

    float acc[4][4][4];
#pragma unroll
    for (int i = 0; i < 4; i++)
#pragma unroll
        for (int j = 0; j < 4; j++)
#pragma unroll
            for (int e = 0; e < 4; e++) acc[i][j][e] = 0.f;

    prefetch(0, 0);

    // ldmatrix lane addressing (within-tile offsets, constant across chunks)
    const int a_row = lane & 15;          // + mi*16 + wm*64
    const int a_kc  = lane >> 4;          // + kk*2
    const int b_row = (lane & 7) + ((lane >> 4) << 3);  // + nf*16 + wn*32
    const int b_kc  = (lane >> 3) & 1;                  // + kk*2

    for (int c = 0; c < NC; c++) {
        const int s = c & 1;
        if (c + 1 < NC) { prefetch(c + 1, s ^ 1); cp_wait<1>(); }
        else            { cp_wait<0>(); }
        __syncthreads();

        const uint32_t stg = sb + s * STAGE_BYTES;
#pragma unroll
        for (int kk = 0; kk < 2; kk++) {
            uint32_t ah[4][4], al[4][4];
#pragma unroll
            for (int mi = 0; mi < 4; mi++) {
                int row = wm * 64 + mi * 16 + a_row;
                uint32_t off = swoff(row, kk * 2 + a_kc);
                ldmx4(ah[mi], stg + 0 * TILE_BYTES + off);
                ldmx4(al[mi], stg + 1 * TILE_BYTES + off);
            }
            uint32_t bh[2][4], bl[2][4];
#pragma unroll
            for (int nf = 0; nf < 2; nf++) {
                int row = wn * 32 + nf * 16 + b_row;
                uint32_t off = swoff(row, kk * 2 + b_kc);
                ldmx4(bh[nf], stg + 2 * TILE_BYTES + off);
                ldmx4(bl[nf], stg + 3 * TILE_BYTES + off);
            }
#pragma unroll
            for (int mi = 0; mi < 4; mi++)
#pragma unroll
                for (int ni = 0; ni < 4; ni++) {
                    int nf = ni >> 1, p = (ni & 1) * 2;
                    mma16816(acc[mi][ni], ah[mi], bh[nf][p], bh[nf][p + 1]);
                    mma16816(acc[mi][ni], ah[mi], bl[nf][p], bl[nf][p + 1]);
                    mma16816(acc[mi][ni], al[mi], bh[nf][p], bh[nf][p + 1]);
                }
        }
        __syncthreads();
    }

    // epilogue: direct fp32 stores
#pragma unroll
    for (int mi = 0; mi < 4; mi++) {
        int gr = r0 + wm * 64 + mi * 16 + (lane >> 2);
#pragma unroll
        for (int ni = 0; ni < 4; ni++) {
            int gc = c0 + wn * 32 + ni * 8 + (lane & 3) * 2;
            *(float2*)&C[(size_t)gr * N + gc]       = make_float2(acc[mi][ni][0], acc[mi][ni][1]);
            *(float2*)&C[(size_t)(gr + 8) * N + gc] = make_float2(acc[mi][ni][2], acc[mi][ni][3]);
        }
    }
}

// ---------------- RoPE -----------------------------------------------------
__global__ void rope_kernel(float* __restrict__ X, const float* __restrict__ cosb,
                            const float* __restrict__ sinb, int nheads) {
    int idx = blockIdx.x * blockDim.x + threadIdx.x;
    int total = S_LEN * nheads * 64;
    if (idx >= total) return;
    int d = idx & 63;
    int h = (idx >> 6) % nheads;
    int s = idx / (64 * nheads);
    float c1 = cosb[s * HD + d],      s1 = sinb[s * HD + d];
    float c2 = cosb[s * HD + d + 64], s2 = sinb[s * HD + d + 64];
    float* p = X + (size_t)s * nheads * HD + h * HD;
    float x1 = p[d], x2 = p[d + 64];
    p[d]      = x1 * c1 - x2 * s1;
    p[d + 64] = x2 * c2 + x1 * s2;
}

// ---------------- Flash attention (fp32, causal, GQA 4:1) ------------------
#define FBM 64
#define FBN 64
#define FLD 132
#define PLD 68
#define FLASH_SMEM ((3 * 64 * FLD + 64 * PLD + 192) * 4)

__global__ __launch_bounds__(256, 1)
void flash_attn(const float* __restrict__ Q, const float* __restrict__ Kb,
                const float* __restrict__ Vb, float* __restrict__ O) {
    extern __shared__ float smf[];
    float* Qs   = smf;
    float* Ks   = Qs + 64 * FLD;
    float* Vs   = Ks + 64 * FLD;
    float* Ps   = Vs + 64 * FLD;
    float* mrow = Ps + 64 * PLD;
    float* lrow = mrow + 64;
    float* arow = lrow + 64;

    const int tid = threadIdx.x;
    const int qb = blockIdx.x, h = blockIdx.y;
    const int kv = h >> 2;
    const int q0 = qb * FBM;

    {
        int m  = tid >> 5;
        int d4 = tid & 31;
#pragma unroll
        for (int it = 0; it < 8; it++) {
            int mm = m + it * 8;
            *(float4*)&Qs[mm * FLD + d4 * 4] =
                *(const float4*)&Q[(size_t)(q0 + mm) * (NH * HD) + h * HD + d4 * 4];
        }
    }
    if (tid < 64) { mrow[tid] = -1e30f; lrow[tid] = 0.f; }

    float oacc[4][8];
#pragma unroll
    for (int i = 0; i < 4; i++)
#pragma unroll
        for (int j = 0; j < 8; j++) oacc[i][j] = 0.f;

    const int tmS = tid >> 4, tnS = tid & 15;
    const int trow = tid >> 4, tcol = tid & 15;
    const float scale = 0.08838834764831845f;

    for (int jb = 0; jb <= qb; jb++) {
        const int k0 = jb * FBN;
        __syncthreads();
        {
            int n  = tid >> 5;
            int d4 = tid & 31;
#pragma unroll
            for (int it = 0; it < 8; it++) {
                int nn = n + it * 8;
                size_t gi = (size_t)(k0 + nn) * (NKV * HD) + kv * HD + d4 * 4;
                *(float4*)&Ks[nn * FLD + d4 * 4] = *(const float4*)&Kb[gi];
                *(float4*)&Vs[nn * FLD + d4 * 4] = *(const float4*)&Vb[gi];
            }
        }
        __syncthreads();

        float sacc[4][4];
#pragma unroll
        for (int i = 0; i < 4; i++)
#pragma unroll
            for (int j = 0; j < 4; j++) sacc[i][j] = 0.f;

#pragma unroll 4
        for (int d4 = 0; d4 < 32; d4++) {
            float4 a[4], b[4];
#pragma unroll
            for (int i = 0; i < 4; i++)
                a[i] = *(const float4*)&Qs[(tmS * 4 + i) * FLD + d4 * 4];
#pragma unroll
            for (int j = 0; j < 4; j++)
                b[j] = *(const float4*)&Ks[(tnS + 16 * j) * FLD + d4 * 4];
#pragma unroll
            for (int i = 0; i < 4; i++)
#pragma unroll
                for (int j = 0; j < 4; j++)
                    sacc[i][j] += a[i].x * b[j].x + a[i].y * b[j].y +
                                  a[i].z * b[j].z + a[i].w * b[j].w;
        }
        const bool diag = (jb == qb);
#pragma unroll
        for (int i = 0; i < 4; i++) {
            int gr = q0 + tmS * 4 + i;
#pragma unroll
            for (int j = 0; j < 4; j++) {
                int gc = k0 + tnS + 16 * j;
                float sv = sacc[i][j] * scale;
                if (diag && gc > gr) sv = -1e30f;
                Ps[(tnS + 16 * j) * PLD + (tmS * 4 + i)] = sv;
            }
        }
        __syncthreads();

        {
            int r = tid >> 2, part = tid & 3;
            float lm = -1e30f;
#pragma unroll
            for (int nn = 0; nn < 16; nn++)
                lm = fmaxf(lm, Ps[(part * 16 + nn) * PLD + r]);
            lm = fmaxf(lm, __shfl_xor_sync(0xffffffffu, lm, 1));
            lm = fmaxf(lm, __shfl_xor_sync(0xffffffffu, lm, 2));
            float mprev = mrow[r];
            float mnew  = fmaxf(mprev, lm);
            float psum = 0.f;
#pragma unroll
            for (int nn = 0; nn < 16; nn++) {
                int off = (part * 16 + nn) * PLD + r;
                float p = expf(Ps[off] - mnew);
                Ps[off] = p;
                psum += p;
            }
            psum += __shfl_xor_sync(0xffffffffu, psum, 1);
            psum += __shfl_xor_sync(0xffffffffu, psum, 2);
            if (part == 0) {
                float alpha = expf(mprev - mnew);
                arow[r] = alpha;
                mrow[r] = mnew;
                lrow[r] = lrow[r] * alpha + psum;
            }
        }
        __syncthreads();

        {
#pragma unroll
            for (int i = 0; i < 4; i++) {
                float al = arow[trow * 4 + i];
#pragma unroll
                for (int j = 0; j < 8; j++) oacc[i][j] *= al;
            }
#pragma unroll 2
            for (int n = 0; n < 64; n++) {
                float4 p4 = *(const float4*)&Ps[n * PLD + trow * 4];
                float4 va = *(const float4*)&Vs[n * FLD + tcol * 4];
                float4 vb = *(const float4*)&Vs[n * FLD + tcol * 4 + 64];
                float pp[4] = {p4.x, p4.y, p4.z, p4.w};
                float vv[8] = {va.x, va.y, va.z, va.w, vb.x, vb.y, vb.z, vb.w};
#pragma unroll
                for (int i = 0; i < 4; i++)
#pragma unroll
                    for (int j = 0; j < 8; j++) oacc[i][j] += pp[i] * vv[j];
            }
        }
    }
    __syncthreads();

    {
#pragma unroll
        for (int i = 0; i < 4; i++) {
            int gr = q0 + trow * 4 + i;
            float inv = 1.f / lrow[trow * 4 + i];
            float4 v0 = make_float4(oacc[i][0] * inv, oacc[i][1] * inv,
                                    oacc[i][2] * inv, oacc[i][3] * inv);
            float4 v1 = make_float4(oacc[i][4] * inv, oacc[i][5] * inv,
                                    oacc[i][6] * inv, oacc[i][7] * inv);
            *(float4*)&O[(size_t)gr * (NH * HD) + h * HD + tcol * 4]      = v0;
            *(float4*)&O[(size_t)gr * (NH * HD) + h * HD + tcol * 4 + 64] = v1;
        }
    }
}

// ---------------- launch ----------------------------------------------------
extern "C" void kernel_launch(void* const* d_in, const int* in_sizes, int n_in,
                              void* d_out, int out_size) {
    const float* hs   = (const float*)d_in[0];
    const float* cosb = (const float*)d_in[1];
    const float* sinb = (const float*)d_in[2];
    const float* Wq   = (const float*)d_in[4];
    const float* Wk   = (const float*)d_in[5];
    const float* Wv   = (const float*)d_in[6];
    const float* Wo   = (const float*)d_in[7];
    float* out = (float*)d_out;

    float *Qp, *Kp, *Vp, *AOp;
    cudaGetSymbolAddress((void**)&Qp,  g_Q);
    cudaGetSymbolAddress((void**)&Kp,  g_K);
    cudaGetSymbolAddress((void**)&Vp,  g_V);
    cudaGetSymbolAddress((void**)&AOp, g_AO);
    __nv_bfloat16 *hsH, *hsL, *wqH, *wqL, *wkH, *wkL, *wvH, *wvL, *woH, *woL, *aoH, *aoL;
    cudaGetSymbolAddress((void**)&hsH, g_hs_hi); cudaGetSymbolAddress((void**)&hsL, g_hs_lo);
    cudaGetSymbolAddress((void**)&wqH, g_wq_hi); cudaGetSymbolAddress((void**)&wqL, g_wq_lo);
    cudaGetSymbolAddress((void**)&wkH, g_wk_hi); cudaGetSymbolAddress((void**)&wkL, g_wk_lo);
    cudaGetSymbolAddress((void**)&wvH, g_wv_hi); cudaGetSymbolAddress((void**)&wvL, g_wv_lo);
    cudaGetSymbolAddress((void**)&woH, g_wo_hi); cudaGetSymbolAddress((void**)&woL, g_wo_lo);
    cudaGetSymbolAddress((void**)&aoH, g_ao_hi); cudaGetSymbolAddress((void**)&aoL, g_ao_lo);

    cudaFuncSetAttribute(gemm_hmma, cudaFuncAttributeMaxDynamicSharedMemorySize, GEMM_SMEM);
    cudaFuncSetAttribute(flash_attn, cudaFuncAttributeMaxDynamicSharedMemorySize, FLASH_SMEM);

    auto split = [](const float* src, __nv_bfloat16* hi, __nv_bfloat16* lo, int n) {
        int n4 = n / 4;
        split_f32<<<(n4 + 255) / 256, 256>>>((const float4*)src, (uint2*)hi, (uint2*)lo, n4);
    };

    // split inputs
    split(hs, hsH, hsL, S_LEN * HID);
    split(Wq, wqH, wqL, HID * HID);
    split(Wk, wkH, wkL, NKV * HD * HID);
    split(Wv, wvH, wvL, NKV * HD * HID);
    split(Wo, woH, woL, HID * HID);

    // projections (HMMA split-bf16 x3)
    gemm_hmma<<<dim3(HID / 128,      S_LEN / 128), 256, GEMM_SMEM>>>(hsH, hsL, wqH, wqL, Qp, S_LEN, HID,      HID);
    gemm_hmma<<<dim3(NKV * HD / 128, S_LEN / 128), 256, GEMM_SMEM>>>(hsH, hsL, wkH, wkL, Kp, S_LEN, NKV * HD, HID);
    gemm_hmma<<<dim3(NKV * HD / 128, S_LEN / 128), 256, GEMM_SMEM>>>(hsH, hsL, wvH, wvL, Vp, S_LEN, NKV * HD, HID);

    // RoPE
    rope_kernel<<<(S_LEN * NH  * 64 + 255) / 256, 256>>>(Qp, cosb, sinb, NH);
    rope_kernel<<<(S_LEN * NKV * 64 + 255) / 256, 256>>>(Kp, cosb, sinb, NKV);

    // attention (fp32 flash)
    flash_attn<<<dim3(S_LEN / FBM, NH), 256, FLASH_SMEM>>>(Qp, Kp, Vp, AOp);

    // output projection
    split(AOp, aoH, aoL, S_LEN * HID);
    gemm_hmma<<<dim3(HID / 128, S_LEN / 128), 256, GEMM_SMEM>>>(aoH, aoL, woH, woL, out, S_LEN, HID, HID);
}

// round 5
// speedup vs baseline: 2.7443x; 1.4608x over previous
#include <cuda_runtime.h>
#include <cuda_bf16.h>
#include <math.h>
#include <cstdint>

#define S_LEN 2048
#define HID   4096
#define NH    32
#define NKV   8
#define HD    128

// ---------------- scratch (static device globals; no allocations) -----------
__device__ float g_Q [S_LEN * NH  * HD];
__device__ float g_K [S_LEN * NKV * HD];
__device__ float g_V [S_LEN * NKV * HD];
__device__ float g_AO[S_LEN * NH  * HD];

__device__ __nv_bfloat16 g_hs_hi[S_LEN * HID],      g_hs_lo[S_LEN * HID];
__device__ __nv_bfloat16 g_wq_hi[HID * HID],        g_wq_lo[HID * HID];
__device__ __nv_bfloat16 g_wk_hi[NKV * HD * HID],   g_wk_lo[NKV * HD * HID];
__device__ __nv_bfloat16 g_wv_hi[NKV * HD * HID],   g_wv_lo[NKV * HD * HID];
__device__ __nv_bfloat16 g_wo_hi[HID * HID],        g_wo_lo[HID * HID];
__device__ __nv_bfloat16 g_ao_hi[S_LEN * HID],      g_ao_lo[S_LEN * HID];
// attention operands (bf16 hi/lo)
__device__ __nv_bfloat16 g_q_hi[S_LEN * NH  * HD],  g_q_lo[S_LEN * NH  * HD];
__device__ __nv_bfloat16 g_k_hi[S_LEN * NKV * HD],  g_k_lo[S_LEN * NKV * HD];
__device__ __nv_bfloat16 g_v_hi[S_LEN * NKV * HD],  g_v_lo[S_LEN * NKV * HD];

// ---------------- common PTX helpers ----------------------------------------
__device__ __forceinline__ uint32_t smem_u32(const void* p) {
    uint32_t a;
    asm("{ .reg .u64 t; cvta.to.shared.u64 t, %1; cvt.u32.u64 %0, t; }" : "=r"(a) : "l"(p));
    return a;
}
__device__ __forceinline__ void cp16(uint32_t dst, const void* src) {
    asm volatile("cp.async.cg.shared.global [%0], [%1], 16;" :: "r"(dst), "l"(src) : "memory");
}
#define CP_COMMIT() asm volatile("cp.async.commit_group;" ::: "memory")
template <int N> __device__ __forceinline__ void cp_wait() {
    asm volatile("cp.async.wait_group %0;" :: "n"(N) : "memory");
}
__device__ __forceinline__ void ldmx4(uint32_t* r, uint32_t addr) {
    asm volatile("ldmatrix.sync.aligned.m8n8.x4.shared.b16 {%0,%1,%2,%3}, [%4];"
                 : "=r"(r[0]), "=r"(r[1]), "=r"(r[2]), "=r"(r[3]) : "r"(addr));
}
__device__ __forceinline__ void ldmx4t(uint32_t* r, uint32_t addr) {
    asm volatile("ldmatrix.sync.aligned.m8n8.x4.trans.shared.b16 {%0,%1,%2,%3}, [%4];"
                 : "=r"(r[0]), "=r"(r[1]), "=r"(r[2]), "=r"(r[3]) : "r"(addr));
}
__device__ __forceinline__ void mma16816(float* d, const uint32_t* a, uint32_t b0, uint32_t b1) {
    asm volatile(
        "mma.sync.aligned.m16n8k16.row.col.f32.bf16.bf16.f32 "
        "{%0,%1,%2,%3}, {%4,%5,%6,%7}, {%8,%9}, {%0,%1,%2,%3};"
        : "+f"(d[0]), "+f"(d[1]), "+f"(d[2]), "+f"(d[3])
        : "r"(a[0]), "r"(a[1]), "r"(a[2]), "r"(a[3]), "r"(b0), "r"(b1));
}
__device__ __forceinline__ uint32_t pack_bf16(float a, float b) {
    return ((uint32_t)__bfloat16_as_ushort(__float2bfloat16_rn(b)) << 16) |
           __bfloat16_as_ushort(__float2bfloat16_rn(a));
}
__device__ __forceinline__ float ex2f(float x) {
    float y;
    asm("ex2.approx.ftz.f32 %0, %1;" : "=f"(y) : "f"(x));
    return y;
}

// ---------------- split kernels ---------------------------------------------
__global__ void split_f32(const float4* __restrict__ x,
                          uint2* __restrict__ hi, uint2* __restrict__ lo, int n4) {
    int i = blockIdx.x * blockDim.x + threadIdx.x;
    if (i >= n4) return;
    float4 v = x[i];
    float xs[4] = {v.x, v.y, v.z, v.w};
    unsigned short h[4], l[4];
#pragma unroll
    for (int j = 0; j < 4; j++) {
        __nv_bfloat16 hb = __float2bfloat16_rn(xs[j]);
        float r = xs[j] - __bfloat162float(hb);
        h[j] = __bfloat16_as_ushort(hb);
        l[j] = __bfloat16_as_ushort(__float2bfloat16_rn(r));
    }
    hi[i] = make_uint2(((uint32_t)h[1] << 16) | h[0], ((uint32_t)h[3] << 16) | h[2]);
    lo[i] = make_uint2(((uint32_t)l[1] << 16) | l[0], ((uint32_t)l[3] << 16) | l[2]);
}

// RoPE + (optional scale) + split into bf16 hi/lo
__global__ void rope_split(const float* __restrict__ X, const float* __restrict__ cosb,
                           const float* __restrict__ sinb,
                           __nv_bfloat16* __restrict__ hi, __nv_bfloat16* __restrict__ lo,
                           int nheads, float sc) {
    int idx = blockIdx.x * blockDim.x + threadIdx.x;
    int total = S_LEN * nheads * 32;
    if (idx >= total) return;
    int d = (idx & 31) * 2;
    int hh = (idx >> 5) % nheads;
    int s = idx / (32 * nheads);
    size_t base = (size_t)s * nheads * HD + hh * HD;
    float2 x1 = *(const float2*)(X + base + d);
    float2 x2 = *(const float2*)(X + base + d + 64);
    float2 c1 = *(const float2*)(cosb + s * HD + d);
    float2 s1 = *(const float2*)(sinb + s * HD + d);
    float2 c2 = *(const float2*)(cosb + s * HD + d + 64);
    float2 s2 = *(const float2*)(sinb + s * HD + d + 64);
    float o[4] = { (x1.x * c1.x - x2.x * s1.x) * sc, (x1.y * c1.y - x2.y * s1.y) * sc,
                   (x2.x * c2.x + x1.x * s2.x) * sc, (x2.y * c2.y + x1.y * s2.y) * sc };
    unsigned short h[4], l[4];
#pragma unroll
    for (int j = 0; j < 4; j++) {
        __nv_bfloat16 hb = __float2bfloat16_rn(o[j]);
        h[j] = __bfloat16_as_ushort(hb);
        l[j] = __bfloat16_as_ushort(__float2bfloat16_rn(o[j] - __bfloat162float(hb)));
    }
    *(uint32_t*)(hi + base + d)      = ((uint32_t)h[1] << 16) | h[0];
    *(uint32_t*)(hi + base + d + 64) = ((uint32_t)h[3] << 16) | h[2];
    *(uint32_t*)(lo + base + d)      = ((uint32_t)l[1] << 16) | l[0];
    *(uint32_t*)(lo + base + d + 64) = ((uint32_t)l[3] << 16) | l[2];
}

// =================== HMMA split-bf16 GEMM: C = A * B^T ======================
#define GBK 32
#define TILE_BYTES 8192
#define STAGE_BYTES (4 * TILE_BYTES)
#define GEMM_STAGES 3
#define GEMM_SMEM (GEMM_STAGES * STAGE_BYTES)   // 96 KB

__device__ __forceinline__ uint32_t swoff(int row, int kc) {
    return (uint32_t)(row * 64 + ((kc ^ ((row >> 1) & 3)) << 4));
}

__global__ __launch_bounds__(256, 1)
void gemm_hmma(const __nv_bfloat16* __restrict__ Ahi, const __nv_bfloat16* __restrict__ Alo,
               const __nv_bfloat16* __restrict__ Bhi, const __nv_bfloat16* __restrict__ Blo,
               float* __restrict__ C, int M, int N, int K) {
    extern __shared__ char sm[];
    const uint32_t sb = smem_u32(sm);
    const int tid = threadIdx.x;
    const int wid = tid >> 5, lane = tid & 31;
    const int wm = wid >> 2, wn = wid & 3;
    const int r0 = blockIdx.y * 128;
    const int c0 = blockIdx.x * 128;
    const int NC = K / GBK;

    const __nv_bfloat16* gsrc[4] = {
        Ahi + (size_t)r0 * K, Alo + (size_t)r0 * K,
        Bhi + (size_t)c0 * K, Blo + (size_t)c0 * K };

    auto prefetch = [&](int c, int s) {
        uint32_t sbase = sb + s * STAGE_BYTES;
#pragma unroll
        for (int t = 0; t < 4; t++) {
#pragma unroll
            for (int it = 0; it < 2; it++) {
                int u = tid + it * 256;
                int row = u >> 2, kc = u & 3;
                cp16(sbase + t * TILE_BYTES + swoff(row, kc),
                     gsrc[t] + (size_t)row * K + c * GBK + kc * 8);
            }
        }
        CP_COMMIT();
    };

    float acc[4][4][4];
#pragma unroll
    for (int i = 0; i < 4; i++)
#pragma unroll
        for (int j = 0; j < 4; j++)
#pragma unroll
            for (int e = 0; e < 4; e++) acc[i][j][e] = 0.f;

    prefetch(0, 0);
    prefetch(1, 1);

    const int a_row = lane & 15;
    const int a_kc  = lane >> 4;
    const int b_row = (lane & 7) + ((lane >> 4) << 3);
    const int b_kc  = (lane >> 3) & 1;

    int s = 0;
    for (int c = 0; c < NC; c++) {
        if (c + 2 < NC) { prefetch(c + 2, (c + 2) % GEMM_STAGES); cp_wait<2>(); }
        else if (c + 1 < NC) cp_wait<1>();
        else cp_wait<0>();
        __syncthreads();

        const uint32_t stg = sb + s * STAGE_BYTES;
#pragma unroll
        for (int kk = 0; kk < 2; kk++) {
            uint32_t ah[4][4], al[4][4];
#pragma unroll
            for (int mi = 0; mi < 4; mi++) {
                int row = wm * 64 + mi * 16 + a_row;
                uint32_t off = swoff(row, kk * 2 + a_kc);
                ldmx4(ah[mi], stg + 0 * TILE_BYTES + off);
                ldmx4(al[mi], stg + 1 * TILE_BYTES + off);
            }
            uint32_t bh[2][4], bl[2][4];
#pragma unroll
            for (int nf = 0; nf < 2; nf++) {
                int row = wn * 32 + nf * 16 + b_row;
                uint32_t off = swoff(row, kk * 2 + b_kc);
                ldmx4(bh[nf], stg + 2 * TILE_BYTES + off);
                ldmx4(bl[nf], stg + 3 * TILE_BYTES + off);
            }
#pragma unroll
            for (int mi = 0; mi < 4; mi++)
#pragma unroll
                for (int ni = 0; ni < 4; ni++) {
                    int nf = ni >> 1, p = (ni & 1) * 2;
                    mma16816(acc[mi][ni], ah[mi], bh[nf][p], bh[nf][p + 1]);
                    mma16816(acc[mi][ni], ah[mi], bl[nf][p], bl[nf][p + 1]);
                    mma16816(acc[mi][ni], al[mi], bh[nf][p], bh[nf][p + 1]);
                }
        }
        __syncthreads();
        s = (s + 1 == GEMM_STAGES) ? 0 : s + 1;
    }

#pragma unroll
    for (int mi = 0; mi < 4; mi++) {
        int gr = r0 + wm * 64 + mi * 16 + (lane >> 2);
#pragma unroll
        for (int ni = 0; ni < 4; ni++) {
            int gc = c0 + wn * 32 + ni * 8 + (lane & 3) * 2;
            *(float2*)&C[(size_t)gr * N + gc]       = make_float2(acc[mi][ni][0], acc[mi][ni][1]);
            *(float2*)&C[(size_t)(gr + 8) * N + gc] = make_float2(acc[mi][ni][2], acc[mi][ni][3]);
        }
    }
}

// =================== Flash attention: HMMA bf16x3, causal, GQA ==============
// CTA: 128 q-rows x 1 head. 8 warps, each warp 16 q-rows. K-tile = 64 keys.
// smem: Qhi(32K) Qlo(32K), 2 stages x {Khi,Klo,Vhi,Vlo}(16K each) = 192K total
#define FS_QH 0
#define FS_QL 32768
#define FS_KV 65536
#define FS_STAGE 65536
#define FLASH_SMEM (FS_KV + 2 * FS_STAGE)   // 196608

__device__ __forceinline__ uint32_t fladdr(uint32_t base, int rb, int cb,
                                           int l7, int selr, int selc) {
    int r = rb + l7 + selr;
    int c = cb + selc;
    return base + r * 256 + (((c ^ (r & 7)) & 15) << 4);
}

__global__ __launch_bounds__(256, 1)
void flash_hmma(const __nv_bfloat16* __restrict__ Qhi, const __nv_bfloat16* __restrict__ Qlo,
                const __nv_bfloat16* __restrict__ Khi, const __nv_bfloat16* __restrict__ Klo,
                const __nv_bfloat16* __restrict__ Vhi, const __nv_bfloat16* __restrict__ Vlo,
                float* __restrict__ AO) {
    extern __shared__ char fsm[];
    const uint32_t sb = smem_u32(fsm);
    const int tid = threadIdx.x;
    const int lane = tid & 31, wm = tid >> 5;
    const int gid = lane >> 2, tig = lane & 3;
    const int l7 = lane & 7, selr = ((lane >> 3) & 1) << 3, selc = lane >> 4;

    const int qb = (int)(gridDim.x - 1 - blockIdx.x);   // big tiles first
    const int h = blockIdx.y;
    const int kv = h >> 2;
    const int q0 = qb * 128;
    const int njb = 2 * (qb + 1);

    // load Q tile (hi+lo) into smem
#pragma unroll
    for (int i = 0; i < 8; i++) {
        int u = tid + i * 256;             // 0..2047
        int row = u >> 4, c = u & 15;
        uint32_t so = (row << 8) + (((c ^ (row & 7))) << 4);
        const size_t gi = (size_t)(q0 + row) * (NH * HD) + h * HD + c * 8;
        cp16(sb + FS_QH + so, Qhi + gi);
        cp16(sb + FS_QL + so, Qlo + gi);
    }
    const __nv_bfloat16* kvsrc[4] = {Khi, Klo, Vhi, Vlo};
    auto prefetch_kv = [&](int jb, int s) {
        uint32_t sbase = sb + FS_KV + s * FS_STAGE;
#pragma unroll
        for (int t = 0; t < 4; t++) {
#pragma unroll
            for (int i = 0; i < 4; i++) {
                int u = tid + i * 256;     // 0..1023
                int row = u >> 4, c = u & 15;
                uint32_t so = (row << 8) + (((c ^ (row & 7))) << 4);
                cp16(sbase + t * 16384 + so,
                     kvsrc[t] + (size_t)(jb * 64 + row) * (NKV * HD) + kv * HD + c * 8);
            }
        }
        CP_COMMIT();
    };
    prefetch_kv(0, 0);   // commit covers Q too

    float oacc[16][4];
#pragma unroll
    for (int j = 0; j < 16; j++)
#pragma unroll
        for (int e = 0; e < 4; e++) oacc[j][e] = 0.f;
    float m0 = -1e30f, m1 = -1e30f, l0 = 0.f, l1 = 0.f;

    const int wrow0 = q0 + wm * 16;

    for (int jb = 0; jb < njb; jb++) {
        if (jb + 1 < njb) { prefetch_kv(jb + 1, (jb + 1) & 1); cp_wait<1>(); }
        else cp_wait<0>();
        __syncthreads();

        const int k0 = jb * 64;
        const bool skip = (k0 > wrow0 + 15);
        if (!skip) {
            const uint32_t stg = sb + FS_KV + (jb & 1) * FS_STAGE;
            // ---- S = Q K^T (split x3) ----
            float sacc[8][4];
#pragma unroll
            for (int j = 0; j < 8; j++)
#pragma unroll
                for (int e = 0; e < 4; e++) sacc[j][e] = 0.f;
#pragma unroll
            for (int ks = 0; ks < 8; ks++) {
                uint32_t ah[4], al[4];
                uint32_t aa = fladdr(sb + FS_QH, wm * 16, 2 * ks, l7, selr, selc);
                ldmx4(ah, aa);
                ldmx4(al, aa + (FS_QL - FS_QH));
#pragma unroll
                for (int g4 = 0; g4 < 4; g4++) {
                    uint32_t bh[4], bl[4];
                    uint32_t ba = fladdr(stg, 16 * g4, 2 * ks, l7, selr, selc);
                    ldmx4(bh, ba);
                    ldmx4(bl, ba + 16384);
                    mma16816(sacc[2 * g4],     ah, bh[0], bh[2]);
                    mma16816(sacc[2 * g4],     ah, bl[0], bl[2]);
                    mma16816(sacc[2 * g4],     al, bh[0], bh[2]);
                    mma16816(sacc[2 * g4 + 1], ah, bh[1], bh[3]);
                    mma16816(sacc[2 * g4 + 1], ah, bl[1], bl[3]);
                    mma16816(sacc[2 * g4 + 1], al, bh[1], bh[3]);
                }
            }
            // ---- causal mask (scores are in log2 units; Q was pre-scaled) ----
            if (k0 + 63 > wrow0) {
                int row0 = wrow0 + gid;
#pragma unroll
                for (int j = 0; j < 8; j++) {
                    int col = k0 + 8 * j + 2 * tig;
                    if (col > row0)         sacc[j][0] = -1e30f;
                    if (col + 1 > row0)     sacc[j][1] = -1e30f;
                    if (col > row0 + 8)     sacc[j][2] = -1e30f;
                    if (col + 1 > row0 + 8) sacc[j][3] = -1e30f;
                }
            }
            // ---- online softmax (register fragments) ----
            float tm0 = -1e30f, tm1 = -1e30f;
#pragma unroll
            for (int j = 0; j < 8; j++) {
                tm0 = fmaxf(tm0, fmaxf(sacc[j][0], sacc[j][1]));
                tm1 = fmaxf(tm1, fmaxf(sacc[j][2], sacc[j][3]));
            }
            tm0 = fmaxf(tm0, __shfl_xor_sync(0xffffffffu, tm0, 1));
            tm0 = fmaxf(tm0, __shfl_xor_sync(0xffffffffu, tm0, 2));
            tm1 = fmaxf(tm1, __shfl_xor_sync(0xffffffffu, tm1, 1));
            tm1 = fmaxf(tm1, __shfl_xor_sync(0xffffffffu, tm1, 2));
            float mn0 = fmaxf(m0, tm0), mn1 = fmaxf(m1, tm1);
            float a0 = ex2f(m0 - mn0), a1 = ex2f(m1 - mn1);
            m0 = mn0; m1 = mn1;
            float rs0 = 0.f, rs1 = 0.f;
#pragma unroll
            for (int j = 0; j < 8; j++) {
                sacc[j][0] = ex2f(sacc[j][0] - mn0);
                sacc[j][1] = ex2f(sacc[j][1] - mn0);
                sacc[j][2] = ex2f(sacc[j][2] - mn1);
                sacc[j][3] = ex2f(sacc[j][3] - mn1);
                rs0 += sacc[j][0] + sacc[j][1];
                rs1 += sacc[j][2] + sacc[j][3];
            }
            rs0 += __shfl_xor_sync(0xffffffffu, rs0, 1);
            rs0 += __shfl_xor_sync(0xffffffffu, rs0, 2);
            rs1 += __shfl_xor_sync(0xffffffffu, rs1, 1);
            rs1 += __shfl_xor_sync(0xffffffffu, rs1, 2);
            l0 = l0 * a0 + rs0;
            l1 = l1 * a1 + rs1;
#pragma unroll
            for (int j = 0; j < 16; j++) {
                oacc[j][0] *= a0; oacc[j][1] *= a0;
                oacc[j][2] *= a1; oacc[j][3] *= a1;
            }
            // ---- O += P V (split x3) ----
#pragma unroll
            for (int ks = 0; ks < 4; ks++) {
                float r00 = sacc[2*ks][0]   - __bfloat162float(__float2bfloat16_rn(sacc[2*ks][0]));
                float r01 = sacc[2*ks][1]   - __bfloat162float(__float2bfloat16_rn(sacc[2*ks][1]));
                float r02 = sacc[2*ks][2]   - __bfloat162float(__float2bfloat16_rn(sacc[2*ks][2]));
                float r03 = sacc[2*ks][3]   - __bfloat162float(__float2bfloat16_rn(sacc[2*ks][3]));
                float r10 = sacc[2*ks+1][0] - __bfloat162float(__float2bfloat16_rn(sacc[2*ks+1][0]));
                float r11 = sacc[2*ks+1][1] - __bfloat162float(__float2bfloat16_rn(sacc[2*ks+1][1]));
                float r12 = sacc[2*ks+1][2] - __bfloat162float(__float2bfloat16_rn(sacc[2*ks+1][2]));
                float r13 = sacc[2*ks+1][3] - __bfloat162float(__float2bfloat16_rn(sacc[2*ks+1][3]));
                uint32_t phi[4] = { pack_bf16(sacc[2*ks][0],   sacc[2*ks][1]),
                                    pack_bf16(sacc[2*ks][2],   sacc[2*ks][3]),
                                    pack_bf16(sacc[2*ks+1][0], sacc[2*ks+1][1]),
                                    pack_bf16(sacc[2*ks+1][2], sacc[2*ks+1][3]) };
                uint32_t plo[4] = { pack_bf16(r00, r01), pack_bf16(r02, r03),
                                    pack_bf16(r10, r11), pack_bf16(r12, r13) };
#pragma unroll
                for (int g = 0; g < 8; g++) {
                    uint32_t vh[4], vl[4];
                    uint32_t va = fladdr(stg + 32768, 16 * ks, 2 * g, l7, selr, selc);
                    ldmx4t(vh, va);
                    ldmx4t(vl, va + 16384);
                    mma16816(oacc[2 * g],     phi, vh[0], vh[1]);
                    mma16816(oacc[2 * g],     phi, vl[0], vl[1]);
                    mma16816(oacc[2 * g],     plo, vh[0], vh[1]);
                    mma16816(oacc[2 * g + 1], phi, vh[2], vh[3]);
                    mma16816(oacc[2 * g + 1], phi, vl[2], vl[3]);
                    mma16816(oacc[2 * g + 1], plo, vh[2], vh[3]);
                }
            }
        }
        __syncthreads();
    }

    // ---- normalize + write ----
    const float inv0 = 1.f / l0, inv1 = 1.f / l1;
    const int row0 = wrow0 + gid;
#pragma unroll
    for (int j = 0; j < 16; j++) {
        size_t d = (size_t)h * HD + 8 * j + 2 * tig;
        *(float2*)&AO[(size_t)row0 * (NH * HD) + d] =
            make_float2(oacc[j][0] * inv0, oacc[j][1] * inv0);
        *(float2*)&AO[(size_t)(row0 + 8) * (NH * HD) + d] =
            make_float2(oacc[j][2] * inv1, oacc[j][3] * inv1);
    }
}

// ---------------- launch ----------------------------------------------------
extern "C" void kernel_launch(void* const* d_in, const int* in_sizes, int n_in,
                              void* d_out, int out_size) {
    const float* hs   = (const float*)d_in[0];
    const float* cosb = (const float*)d_in[1];
    const float* sinb = (const float*)d_in[2];
    const float* Wq   = (const float*)d_in[4];
    const float* Wk   = (const float*)d_in[5];
    const float* Wv   = (const float*)d_in[6];
    const float* Wo   = (const float*)d_in[7];
    float* out = (float*)d_out;

    float *Qp, *Kp, *Vp, *AOp;
    cudaGetSymbolAddress((void**)&Qp,  g_Q);
    cudaGetSymbolAddress((void**)&Kp,  g_K);
    cudaGetSymbolAddress((void**)&Vp,  g_V);
    cudaGetSymbolAddress((void**)&AOp, g_AO);
    __nv_bfloat16 *hsH, *hsL, *wqH, *wqL, *wkH, *wkL, *wvH, *wvL, *woH, *woL, *aoH, *aoL;
    __nv_bfloat16 *qH, *qL, *kH, *kL, *vH, *vL;
    cudaGetSymbolAddress((void**)&hsH, g_hs_hi); cudaGetSymbolAddress((void**)&hsL, g_hs_lo);
    cudaGetSymbolAddress((void**)&wqH, g_wq_hi); cudaGetSymbolAddress((void**)&wqL, g_wq_lo);
    cudaGetSymbolAddress((void**)&wkH, g_wk_hi); cudaGetSymbolAddress((void**)&wkL, g_wk_lo);
    cudaGetSymbolAddress((void**)&wvH, g_wv_hi); cudaGetSymbolAddress((void**)&wvL, g_wv_lo);
    cudaGetSymbolAddress((void**)&woH, g_wo_hi); cudaGetSymbolAddress((void**)&woL, g_wo_lo);
    cudaGetSymbolAddress((void**)&aoH, g_ao_hi); cudaGetSymbolAddress((void**)&aoL, g_ao_lo);
    cudaGetSymbolAddress((void**)&qH,  g_q_hi);  cudaGetSymbolAddress((void**)&qL,  g_q_lo);
    cudaGetSymbolAddress((void**)&kH,  g_k_hi);  cudaGetSymbolAddress((void**)&kL,  g_k_lo);
    cudaGetSymbolAddress((void**)&vH,  g_v_hi);  cudaGetSymbolAddress((void**)&vL,  g_v_lo);

    cudaFuncSetAttribute(gemm_hmma, cudaFuncAttributeMaxDynamicSharedMemorySize, GEMM_SMEM);
    cudaFuncSetAttribute(flash_hmma, cudaFuncAttributeMaxDynamicSharedMemorySize, FLASH_SMEM);

    auto split = [](const float* src, __nv_bfloat16* hi, __nv_bfloat16* lo, int n) {
        int n4 = n / 4;
        split_f32<<<(n4 + 255) / 256, 256>>>((const float4*)src, (uint2*)hi, (uint2*)lo, n4);
    };

    // split inputs
    split(hs, hsH, hsL, S_LEN * HID);
    split(Wq, wqH, wqL, HID * HID);
    split(Wk, wkH, wkL, NKV * HD * HID);
    split(Wv, wvH, wvL, NKV * HD * HID);
    split(Wo, woH, woL, HID * HID);

    // projections
    gemm_hmma<<<dim3(HID / 128,      S_LEN / 128), 256, GEMM_SMEM>>>(hsH, hsL, wqH, wqL, Qp, S_LEN, HID,      HID);
    gemm_hmma<<<dim3(NKV * HD / 128, S_LEN / 128), 256, GEMM_SMEM>>>(hsH, hsL, wkH, wkL, Kp, S_LEN, NKV * HD, HID);
    gemm_hmma<<<dim3(NKV * HD / 128, S_LEN / 128), 256, GEMM_SMEM>>>(hsH, hsL, wvH, wvL, Vp, S_LEN, NKV * HD, HID);

    // RoPE + split (Q pre-scaled by softmax_scale * log2(e) => exp2 softmax)
    const float SC = 0.08838834764831845f * 1.4426950408889634f;
    rope_split<<<(S_LEN * NH  * 32 + 255) / 256, 256>>>(Qp, cosb, sinb, qH, qL, NH,  SC);
    rope_split<<<(S_LEN * NKV * 32 + 255) / 256, 256>>>(Kp, cosb, sinb, kH, kL, NKV, 1.0f);
    split(Vp, vH, vL, S_LEN * NKV * HD);

    // attention (HMMA bf16x3 flash)
    flash_hmma<<<dim3(S_LEN / 128, NH), 256, FLASH_SMEM>>>(qH, qL, kH, kL, vH, vL, AOp);

    // output projection
    split(AOp, aoH, aoL, S_LEN * HID);
    gemm_hmma<<<dim3(HID / 128, S_LEN / 128), 256, GEMM_SMEM>>>(aoH, aoL, woH, woL, out, S_LEN, HID, HID);
}

// round 6
// speedup vs baseline: 3.0069x; 1.0957x over previous
#include <cuda_runtime.h>
#include <cuda_bf16.h>
#include <math.h>
#include <cstdint>

#define S_LEN 2048
#define HID   4096
#define NH    32
#define NKV   8
#define HD    128

// ---------------- scratch (static device globals; no allocations) -----------
__device__ float g_Q [S_LEN * NH  * HD];
__device__ float g_K [S_LEN * NKV * HD];

__device__ __nv_bfloat16 g_hs_hi[S_LEN * HID],      g_hs_lo[S_LEN * HID];
__device__ __nv_bfloat16 g_wq_hi[HID * HID],        g_wq_lo[HID * HID];
__device__ __nv_bfloat16 g_wk_hi[NKV * HD * HID],   g_wk_lo[NKV * HD * HID];
__device__ __nv_bfloat16 g_wv_hi[NKV * HD * HID],   g_wv_lo[NKV * HD * HID];
__device__ __nv_bfloat16 g_wo_hi[HID * HID],        g_wo_lo[HID * HID];
__device__ __nv_bfloat16 g_ao_hi[S_LEN * HID],      g_ao_lo[S_LEN * HID];
__device__ __nv_bfloat16 g_q_hi[S_LEN * NH  * HD],  g_q_lo[S_LEN * NH  * HD];
__device__ __nv_bfloat16 g_k_hi[S_LEN * NKV * HD],  g_k_lo[S_LEN * NKV * HD];
__device__ __nv_bfloat16 g_v_hi[S_LEN * NKV * HD],  g_v_lo[S_LEN * NKV * HD];

// ---------------- common PTX helpers ----------------------------------------
__device__ __forceinline__ uint32_t smem_u32(const void* p) {
    uint32_t a;
    asm("{ .reg .u64 t; cvta.to.shared.u64 t, %1; cvt.u32.u64 %0, t; }" : "=r"(a) : "l"(p));
    return a;
}
__device__ __forceinline__ void cp16(uint32_t dst, const void* src) {
    asm volatile("cp.async.cg.shared.global [%0], [%1], 16;" :: "r"(dst), "l"(src) : "memory");
}
#define CP_COMMIT() asm volatile("cp.async.commit_group;" ::: "memory")
template <int N> __device__ __forceinline__ void cp_wait() {
    asm volatile("cp.async.wait_group %0;" :: "n"(N) : "memory");
}
__device__ __forceinline__ void ldmx4(uint32_t* r, uint32_t addr) {
    asm volatile("ldmatrix.sync.aligned.m8n8.x4.shared.b16 {%0,%1,%2,%3}, [%4];"
                 : "=r"(r[0]), "=r"(r[1]), "=r"(r[2]), "=r"(r[3]) : "r"(addr));
}
__device__ __forceinline__ void ldmx4t(uint32_t* r, uint32_t addr) {
    asm volatile("ldmatrix.sync.aligned.m8n8.x4.trans.shared.b16 {%0,%1,%2,%3}, [%4];"
                 : "=r"(r[0]), "=r"(r[1]), "=r"(r[2]), "=r"(r[3]) : "r"(addr));
}
__device__ __forceinline__ void mma16816(float* d, const uint32_t* a, uint32_t b0, uint32_t b1) {
    asm volatile(
        "mma.sync.aligned.m16n8k16.row.col.f32.bf16.bf16.f32 "
        "{%0,%1,%2,%3}, {%4,%5,%6,%7}, {%8,%9}, {%0,%1,%2,%3};"
        : "+f"(d[0]), "+f"(d[1]), "+f"(d[2]), "+f"(d[3])
        : "r"(a[0]), "r"(a[1]), "r"(a[2]), "r"(a[3]), "r"(b0), "r"(b1));
}
__device__ __forceinline__ uint32_t pack_bf16(float a, float b) {
    return ((uint32_t)__bfloat16_as_ushort(__float2bfloat16_rn(b)) << 16) |
           __bfloat16_as_ushort(__float2bfloat16_rn(a));
}
// split (a,b) fp32 -> packed hi pair + packed lo pair
__device__ __forceinline__ void split_pack(float a, float b, uint32_t& hp, uint32_t& lp) {
    __nv_bfloat16 ha = __float2bfloat16_rn(a), hb = __float2bfloat16_rn(b);
    hp = ((uint32_t)__bfloat16_as_ushort(hb) << 16) | __bfloat16_as_ushort(ha);
    lp = pack_bf16(a - __bfloat162float(ha), b - __bfloat162float(hb));
}
__device__ __forceinline__ float ex2f(float x) {
    float y;
    asm("ex2.approx.ftz.f32 %0, %1;" : "=f"(y) : "f"(x));
    return y;
}

// ---------------- split kernels ---------------------------------------------
__global__ void split_f32(const float4* __restrict__ x,
                          uint2* __restrict__ hi, uint2* __restrict__ lo, int n4) {
    int i = blockIdx.x * blockDim.x + threadIdx.x;
    if (i >= n4) return;
    float4 v = x[i];
    float xs[4] = {v.x, v.y, v.z, v.w};
    unsigned short h[4], l[4];
#pragma unroll
    for (int j = 0; j < 4; j++) {
        __nv_bfloat16 hb = __float2bfloat16_rn(xs[j]);
        float r = xs[j] - __bfloat162float(hb);
        h[j] = __bfloat16_as_ushort(hb);
        l[j] = __bfloat16_as_ushort(__float2bfloat16_rn(r));
    }
    hi[i] = make_uint2(((uint32_t)h[1] << 16) | h[0], ((uint32_t)h[3] << 16) | h[2]);
    lo[i] = make_uint2(((uint32_t)l[1] << 16) | l[0], ((uint32_t)l[3] << 16) | l[2]);
}

__global__ void rope_split(const float* __restrict__ X, const float* __restrict__ cosb,
                           const float* __restrict__ sinb,
                           __nv_bfloat16* __restrict__ hi, __nv_bfloat16* __restrict__ lo,
                           int nheads, float sc) {
    int idx = blockIdx.x * blockDim.x + threadIdx.x;
    int total = S_LEN * nheads * 32;
    if (idx >= total) return;
    int d = (idx & 31) * 2;
    int hh = (idx >> 5) % nheads;
    int s = idx / (32 * nheads);
    size_t base = (size_t)s * nheads * HD + hh * HD;
    float2 x1 = *(const float2*)(X + base + d);
    float2 x2 = *(const float2*)(X + base + d + 64);
    float2 c1 = *(const float2*)(cosb + s * HD + d);
    float2 s1 = *(const float2*)(sinb + s * HD + d);
    float2 c2 = *(const float2*)(cosb + s * HD + d + 64);
    float2 s2 = *(const float2*)(sinb + s * HD + d + 64);
    float o[4] = { (x1.x * c1.x - x2.x * s1.x) * sc, (x1.y * c1.y - x2.y * s1.y) * sc,
                   (x2.x * c2.x + x1.x * s2.x) * sc, (x2.y * c2.y + x1.y * s2.y) * sc };
    uint32_t hp0, lp0, hp1, lp1;
    split_pack(o[0], o[1], hp0, lp0);
    split_pack(o[2], o[3], hp1, lp1);
    *(uint32_t*)(hi + base + d)      = hp0;
    *(uint32_t*)(hi + base + d + 64) = hp1;
    *(uint32_t*)(lo + base + d)      = lp0;
    *(uint32_t*)(lo + base + d + 64) = lp1;
}

// =================== HMMA split-bf16 GEMM machinery ==========================
#define GBK 32
#define TILE_BYTES 8192
#define STAGE_BYTES (4 * TILE_BYTES)
#define GEMM_STAGES 3
#define GEMM_SMEM (GEMM_STAGES * STAGE_BYTES)   // 96 KB

__device__ __forceinline__ uint32_t swoff(int row, int kc) {
    return (uint32_t)(row * 64 + ((kc ^ ((row >> 1) & 3)) << 4));
}

// core mainloop: accumulates 128x128 tile (A rows r0, B rows c0), K=HID
struct GemmCore {
    uint32_t sb;
    int tid, lane, wm, wn;
    const __nv_bfloat16* gsrc[4];

    __device__ __forceinline__ void prefetch(int c, int s) {
        uint32_t sbase = sb + s * STAGE_BYTES;
#pragma unroll
        for (int t = 0; t < 4; t++) {
#pragma unroll
            for (int it = 0; it < 2; it++) {
                int u = tid + it * 256;
                int row = u >> 2, kc = u & 3;
                cp16(sbase + t * TILE_BYTES + swoff(row, kc),
                     gsrc[t] + (size_t)row * HID + c * GBK + kc * 8);
            }
        }
        CP_COMMIT();
    }

    __device__ __forceinline__ void run(float acc[4][4][4]) {
#pragma unroll
        for (int i = 0; i < 4; i++)
#pragma unroll
            for (int j = 0; j < 4; j++)
#pragma unroll
                for (int e = 0; e < 4; e++) acc[i][j][e] = 0.f;

        prefetch(0, 0);
        prefetch(1, 1);

        const int a_row = lane & 15;
        const int a_kc  = lane >> 4;
        const int b_row = (lane & 7) + ((lane >> 4) << 3);
        const int b_kc  = (lane >> 3) & 1;
        const int NC = HID / GBK;

        int s = 0;
        for (int c = 0; c < NC; c++) {
            if (c + 2 < NC) { prefetch(c + 2, (c + 2) % GEMM_STAGES); cp_wait<2>(); }
            else if (c + 1 < NC) cp_wait<1>();
            else cp_wait<0>();
            __syncthreads();

            const uint32_t stg = sb + s * STAGE_BYTES;
#pragma unroll
            for (int kk = 0; kk < 2; kk++) {
                uint32_t ah[4][4], al[4][4];
#pragma unroll
                for (int mi = 0; mi < 4; mi++) {
                    int row = wm * 64 + mi * 16 + a_row;
                    uint32_t off = swoff(row, kk * 2 + a_kc);
                    ldmx4(ah[mi], stg + 0 * TILE_BYTES + off);
                    ldmx4(al[mi], stg + 1 * TILE_BYTES + off);
                }
#pragma unroll
                for (int nf = 0; nf < 2; nf++) {
                    uint32_t bh[4], bl[4];
                    int row = wn * 32 + nf * 16 + b_row;
                    uint32_t off = swoff(row, kk * 2 + b_kc);
                    ldmx4(bh, stg + 2 * TILE_BYTES + off);
                    ldmx4(bl, stg + 3 * TILE_BYTES + off);
#pragma unroll
                    for (int mi = 0; mi < 4; mi++)
#pragma unroll
                        for (int nq = 0; nq < 2; nq++) {
                            int ni = nf * 2 + nq, p = nq * 2;
                            mma16816(acc[mi][ni], ah[mi], bh[p], bh[p + 1]);
                            mma16816(acc[mi][ni], ah[mi], bl[p], bl[p + 1]);
                            mma16816(acc[mi][ni], al[mi], bh[p], bh[p + 1]);
                        }
                }
            }
            __syncthreads();
            s = (s + 1 == GEMM_STAGES) ? 0 : s + 1;
        }
    }
};

// -------- fused QKV projection: bx<32 -> Q, 32..39 -> K, 40..47 -> V(split) --
__global__ __launch_bounds__(256, 2)
void gemm_qkv(const __nv_bfloat16* __restrict__ Ahi, const __nv_bfloat16* __restrict__ Alo,
              const __nv_bfloat16* __restrict__ WqH, const __nv_bfloat16* __restrict__ WqL,
              const __nv_bfloat16* __restrict__ WkH, const __nv_bfloat16* __restrict__ WkL,
              const __nv_bfloat16* __restrict__ WvH, const __nv_bfloat16* __restrict__ WvL,
              float* __restrict__ Cq, float* __restrict__ Ck,
              __nv_bfloat16* __restrict__ VH, __nv_bfloat16* __restrict__ VL) {
    extern __shared__ char sm[];
    const int bx = blockIdx.x;
    const int r0 = blockIdx.y * 128;

    int part, c0;
    const __nv_bfloat16 *BH, *BL;
    if (bx < 32)      { part = 0; c0 = bx * 128;        BH = WqH; BL = WqL; }
    else if (bx < 40) { part = 1; c0 = (bx - 32) * 128; BH = WkH; BL = WkL; }
    else              { part = 2; c0 = (bx - 40) * 128; BH = WvH; BL = WvL; }

    GemmCore core;
    core.sb = smem_u32(sm);
    core.tid = threadIdx.x;
    core.lane = core.tid & 31;
    core.wm = (core.tid >> 5) >> 2;
    core.wn = (core.tid >> 5) & 3;
    core.gsrc[0] = Ahi + (size_t)r0 * HID;
    core.gsrc[1] = Alo + (size_t)r0 * HID;
    core.gsrc[2] = BH + (size_t)c0 * HID;
    core.gsrc[3] = BL + (size_t)c0 * HID;

    float acc[4][4][4];
    core.run(acc);

    const int lane = core.lane, wm = core.wm, wn = core.wn;
    if (part == 0 || part == 1) {
        float* C = (part == 0) ? Cq : Ck;
        const int N = (part == 0) ? (NH * HD) : (NKV * HD);
#pragma unroll
        for (int mi = 0; mi < 4; mi++) {
            int gr = r0 + wm * 64 + mi * 16 + (lane >> 2);
#pragma unroll
            for (int ni = 0; ni < 4; ni++) {
                int gc = c0 + wn * 32 + ni * 8 + (lane & 3) * 2;
                *(float2*)&C[(size_t)gr * N + gc]       = make_float2(acc[mi][ni][0], acc[mi][ni][1]);
                *(float2*)&C[(size_t)(gr + 8) * N + gc] = make_float2(acc[mi][ni][2], acc[mi][ni][3]);
            }
        }
    } else {
        const int N = NKV * HD;
#pragma unroll
        for (int mi = 0; mi < 4; mi++) {
            int gr = r0 + wm * 64 + mi * 16 + (lane >> 2);
#pragma unroll
            for (int ni = 0; ni < 4; ni++) {
                int gc = c0 + wn * 32 + ni * 8 + (lane & 3) * 2;
                uint32_t hp, lp;
                split_pack(acc[mi][ni][0], acc[mi][ni][1], hp, lp);
                *(uint32_t*)&VH[(size_t)gr * N + gc] = hp;
                *(uint32_t*)&VL[(size_t)gr * N + gc] = lp;
                split_pack(acc[mi][ni][2], acc[mi][ni][3], hp, lp);
                *(uint32_t*)&VH[(size_t)(gr + 8) * N + gc] = hp;
                *(uint32_t*)&VL[(size_t)(gr + 8) * N + gc] = lp;
            }
        }
    }
}

// -------- generic GEMM (used for O projection) -------------------------------
__global__ __launch_bounds__(256, 2)
void gemm_hmma(const __nv_bfloat16* __restrict__ Ahi, const __nv_bfloat16* __restrict__ Alo,
               const __nv_bfloat16* __restrict__ Bhi, const __nv_bfloat16* __restrict__ Blo,
               float* __restrict__ C, int N) {
    extern __shared__ char sm[];
    const int r0 = blockIdx.y * 128;
    const int c0 = blockIdx.x * 128;

    GemmCore core;
    core.sb = smem_u32(sm);
    core.tid = threadIdx.x;
    core.lane = core.tid & 31;
    core.wm = (core.tid >> 5) >> 2;
    core.wn = (core.tid >> 5) & 3;
    core.gsrc[0] = Ahi + (size_t)r0 * HID;
    core.gsrc[1] = Alo + (size_t)r0 * HID;
    core.gsrc[2] = Bhi + (size_t)c0 * HID;
    core.gsrc[3] = Blo + (size_t)c0 * HID;

    float acc[4][4][4];
    core.run(acc);

    const int lane = core.lane, wm = core.wm, wn = core.wn;
#pragma unroll
    for (int mi = 0; mi < 4; mi++) {
        int gr = r0 + wm * 64 + mi * 16 + (lane >> 2);
#pragma unroll
        for (int ni = 0; ni < 4; ni++) {
            int gc = c0 + wn * 32 + ni * 8 + (lane & 3) * 2;
            *(float2*)&C[(size_t)gr * N + gc]       = make_float2(acc[mi][ni][0], acc[mi][ni][1]);
            *(float2*)&C[(size_t)(gr + 8) * N + gc] = make_float2(acc[mi][ni][2], acc[mi][ni][3]);
        }
    }
}

// =================== Flash attention: HMMA bf16x3, causal, GQA ==============
#define FS_QH 0
#define FS_QL 32768
#define FS_KV 65536
#define FS_STAGE 65536
#define FLASH_SMEM (FS_KV + 2 * FS_STAGE)   // 196608

__device__ __forceinline__ uint32_t fladdr(uint32_t base, int rb, int cb,
                                           int l7, int selr, int selc) {
    int r = rb + l7 + selr;
    int c = cb + selc;
    return base + r * 256 + (((c ^ (r & 7)) & 15) << 4);
}

__global__ __launch_bounds__(256, 1)
void flash_hmma(const __nv_bfloat16* __restrict__ Qhi, const __nv_bfloat16* __restrict__ Qlo,
                const __nv_bfloat16* __restrict__ Khi, const __nv_bfloat16* __restrict__ Klo,
                const __nv_bfloat16* __restrict__ Vhi, const __nv_bfloat16* __restrict__ Vlo,
                __nv_bfloat16* __restrict__ AOhi, __nv_bfloat16* __restrict__ AOlo) {
    extern __shared__ char fsm[];
    const uint32_t sb = smem_u32(fsm);
    const int tid = threadIdx.x;
    const int lane = tid & 31, wm = tid >> 5;
    const int gid = lane >> 2, tig = lane & 3;
    const int l7 = lane & 7, selr = ((lane >> 3) & 1) << 3, selc = lane >> 4;

    const int qb = (int)(gridDim.x - 1 - blockIdx.x);
    const int h = blockIdx.y;
    const int kv = h >> 2;
    const int q0 = qb * 128;
    const int njb = 2 * (qb + 1);

#pragma unroll
    for (int i = 0; i < 8; i++) {
        int u = tid + i * 256;
        int row = u >> 4, c = u & 15;
        uint32_t so = (row << 8) + (((c ^ (row & 7))) << 4);
        const size_t gi = (size_t)(q0 + row) * (NH * HD) + h * HD + c * 8;
        cp16(sb + FS_QH + so, Qhi + gi);
        cp16(sb + FS_QL + so, Qlo + gi);
    }
    const __nv_bfloat16* kvsrc[4] = {Khi, Klo, Vhi, Vlo};
    auto prefetch_kv = [&](int jb, int s) {
        uint32_t sbase = sb + FS_KV + s * FS_STAGE;
#pragma unroll
        for (int t = 0; t < 4; t++) {
#pragma unroll
            for (int i = 0; i < 4; i++) {
                int u = tid + i * 256;
                int row = u >> 4, c = u & 15;
                uint32_t so = (row << 8) + (((c ^ (row & 7))) << 4);
                cp16(sbase + t * 16384 + so,
                     kvsrc[t] + (size_t)(jb * 64 + row) * (NKV * HD) + kv * HD + c * 8);
            }
        }
        CP_COMMIT();
    };
    prefetch_kv(0, 0);

    float oacc[16][4];
#pragma unroll
    for (int j = 0; j < 16; j++)
#pragma unroll
        for (int e = 0; e < 4; e++) oacc[j][e] = 0.f;
    float m0 = -1e30f, m1 = -1e30f, l0 = 0.f, l1 = 0.f;

    const int wrow0 = q0 + wm * 16;

    for (int jb = 0; jb < njb; jb++) {
        if (jb + 1 < njb) { prefetch_kv(jb + 1, (jb + 1) & 1); cp_wait<1>(); }
        else cp_wait<0>();
        __syncthreads();

        const int k0 = jb * 64;
        const bool skip = (k0 > wrow0 + 15);
        if (!skip) {
            const uint32_t stg = sb + FS_KV + (jb & 1) * FS_STAGE;
            float sacc[8][4];
#pragma unroll
            for (int j = 0; j < 8; j++)
#pragma unroll
                for (int e = 0; e < 4; e++) sacc[j][e] = 0.f;
#pragma unroll
            for (int ks = 0; ks < 8; ks++) {
                uint32_t ah[4], al[4];
                uint32_t aa = fladdr(sb + FS_QH, wm * 16, 2 * ks, l7, selr, selc);
                ldmx4(ah, aa);
                ldmx4(al, aa + (FS_QL - FS_QH));
#pragma unroll
                for (int g4 = 0; g4 < 4; g4++) {
                    uint32_t bh[4], bl[4];
                    uint32_t ba = fladdr(stg, 16 * g4, 2 * ks, l7, selr, selc);
                    ldmx4(bh, ba);
                    ldmx4(bl, ba + 16384);
                    mma16816(sacc[2 * g4],     ah, bh[0], bh[2]);
                    mma16816(sacc[2 * g4],     ah, bl[0], bl[2]);
                    mma16816(sacc[2 * g4],     al, bh[0], bh[2]);
                    mma16816(sacc[2 * g4 + 1], ah, bh[1], bh[3]);
                    mma16816(sacc[2 * g4 + 1], ah, bl[1], bl[3]);
                    mma16816(sacc[2 * g4 + 1], al, bh[1], bh[3]);
                }
            }
            if (k0 + 63 > wrow0) {
                int row0 = wrow0 + gid;
#pragma unroll
                for (int j = 0; j < 8; j++) {
                    int col = k0 + 8 * j + 2 * tig;
                    if (col > row0)         sacc[j][0] = -1e30f;
                    if (col + 1 > row0)     sacc[j][1] = -1e30f;
                    if (col > row0 + 8)     sacc[j][2] = -1e30f;
                    if (col + 1 > row0 + 8) sacc[j][3] = -1e30f;
                }
            }
            float tm0 = -1e30f, tm1 = -1e30f;
#pragma unroll
            for (int j = 0; j < 8; j++) {
                tm0 = fmaxf(tm0, fmaxf(sacc[j][0], sacc[j][1]));
                tm1 = fmaxf(tm1, fmaxf(sacc[j][2], sacc[j][3]));
            }
            tm0 = fmaxf(tm0, __shfl_xor_sync(0xffffffffu, tm0, 1));
            tm0 = fmaxf(tm0, __shfl_xor_sync(0xffffffffu, tm0, 2));
            tm1 = fmaxf(tm1, __shfl_xor_sync(0xffffffffu, tm1, 1));
            tm1 = fmaxf(tm1, __shfl_xor_sync(0xffffffffu, tm1, 2));
            float mn0 = fmaxf(m0, tm0), mn1 = fmaxf(m1, tm1);
            float a0 = ex2f(m0 - mn0), a1 = ex2f(m1 - mn1);
            m0 = mn0; m1 = mn1;
            float rs0 = 0.f, rs1 = 0.f;
#pragma unroll
            for (int j = 0; j < 8; j++) {
                sacc[j][0] = ex2f(sacc[j][0] - mn0);
                sacc[j][1] = ex2f(sacc[j][1] - mn0);
                sacc[j][2] = ex2f(sacc[j][2] - mn1);
                sacc[j][3] = ex2f(sacc[j][3] - mn1);
                rs0 += sacc[j][0] + sacc[j][1];
                rs1 += sacc[j][2] + sacc[j][3];
            }
            rs0 += __shfl_xor_sync(0xffffffffu, rs0, 1);
            rs0 += __shfl_xor_sync(0xffffffffu, rs0, 2);
            rs1 += __shfl_xor_sync(0xffffffffu, rs1, 1);
            rs1 += __shfl_xor_sync(0xffffffffu, rs1, 2);
            l0 = l0 * a0 + rs0;
            l1 = l1 * a1 + rs1;
#pragma unroll
            for (int j = 0; j < 16; j++) {
                oacc[j][0] *= a0; oacc[j][1] *= a0;
                oacc[j][2] *= a1; oacc[j][3] *= a1;
            }
#pragma unroll
            for (int ks = 0; ks < 4; ks++) {
                uint32_t phi[4], plo[4];
                split_pack(sacc[2*ks][0],   sacc[2*ks][1],   phi[0], plo[0]);
                split_pack(sacc[2*ks][2],   sacc[2*ks][3],   phi[1], plo[1]);
                split_pack(sacc[2*ks+1][0], sacc[2*ks+1][1], phi[2], plo[2]);
                split_pack(sacc[2*ks+1][2], sacc[2*ks+1][3], phi[3], plo[3]);
#pragma unroll
                for (int g = 0; g < 8; g++) {
                    uint32_t vh[4], vl[4];
                    uint32_t va = fladdr(stg + 32768, 16 * ks, 2 * g, l7, selr, selc);
                    ldmx4t(vh, va);
                    ldmx4t(vl, va + 16384);
                    mma16816(oacc[2 * g],     phi, vh[0], vh[1]);
                    mma16816(oacc[2 * g],     phi, vl[0], vl[1]);
                    mma16816(oacc[2 * g],     plo, vh[0], vh[1]);
                    mma16816(oacc[2 * g + 1], phi, vh[2], vh[3]);
                    mma16816(oacc[2 * g + 1], phi, vl[2], vl[3]);
                    mma16816(oacc[2 * g + 1], plo, vh[2], vh[3]);
                }
            }
        }
        __syncthreads();
    }

    // ---- normalize + split-write bf16 hi/lo ----
    const float inv0 = 1.f / l0, inv1 = 1.f / l1;
    const int row0 = wrow0 + gid;
#pragma unroll
    for (int j = 0; j < 16; j++) {
        size_t d = (size_t)h * HD + 8 * j + 2 * tig;
        uint32_t hp, lp;
        split_pack(oacc[j][0] * inv0, oacc[j][1] * inv0, hp, lp);
        *(uint32_t*)&AOhi[(size_t)row0 * (NH * HD) + d] = hp;
        *(uint32_t*)&AOlo[(size_t)row0 * (NH * HD) + d] = lp;
        split_pack(oacc[j][2] * inv1, oacc[j][3] * inv1, hp, lp);
        *(uint32_t*)&AOhi[(size_t)(row0 + 8) * (NH * HD) + d] = hp;
        *(uint32_t*)&AOlo[(size_t)(row0 + 8) * (NH * HD) + d] = lp;
    }
}

// ---------------- launch ----------------------------------------------------
extern "C" void kernel_launch(void* const* d_in, const int* in_sizes, int n_in,
                              void* d_out, int out_size) {
    const float* hs   = (const float*)d_in[0];
    const float* cosb = (const float*)d_in[1];
    const float* sinb = (const float*)d_in[2];
    const float* Wq   = (const float*)d_in[4];
    const float* Wk   = (const float*)d_in[5];
    const float* Wv   = (const float*)d_in[6];
    const float* Wo   = (const float*)d_in[7];
    float* out = (float*)d_out;

    float *Qp, *Kp;
    cudaGetSymbolAddress((void**)&Qp,  g_Q);
    cudaGetSymbolAddress((void**)&Kp,  g_K);
    __nv_bfloat16 *hsH, *hsL, *wqH, *wqL, *wkH, *wkL, *wvH, *wvL, *woH, *woL, *aoH, *aoL;
    __nv_bfloat16 *qH, *qL, *kH, *kL, *vH, *vL;
    cudaGetSymbolAddress((void**)&hsH, g_hs_hi); cudaGetSymbolAddress((void**)&hsL, g_hs_lo);
    cudaGetSymbolAddress((void**)&wqH, g_wq_hi); cudaGetSymbolAddress((void**)&wqL, g_wq_lo);
    cudaGetSymbolAddress((void**)&wkH, g_wk_hi); cudaGetSymbolAddress((void**)&wkL, g_wk_lo);
    cudaGetSymbolAddress((void**)&wvH, g_wv_hi); cudaGetSymbolAddress((void**)&wvL, g_wv_lo);
    cudaGetSymbolAddress((void**)&woH, g_wo_hi); cudaGetSymbolAddress((void**)&woL, g_wo_lo);
    cudaGetSymbolAddress((void**)&aoH, g_ao_hi); cudaGetSymbolAddress((void**)&aoL, g_ao_lo);
    cudaGetSymbolAddress((void**)&qH,  g_q_hi);  cudaGetSymbolAddress((void**)&qL,  g_q_lo);
    cudaGetSymbolAddress((void**)&kH,  g_k_hi);  cudaGetSymbolAddress((void**)&kL,  g_k_lo);
    cudaGetSymbolAddress((void**)&vH,  g_v_hi);  cudaGetSymbolAddress((void**)&vL,  g_v_lo);

    cudaFuncSetAttribute(gemm_qkv,  cudaFuncAttributeMaxDynamicSharedMemorySize, GEMM_SMEM);
    cudaFuncSetAttribute(gemm_hmma, cudaFuncAttributeMaxDynamicSharedMemorySize, GEMM_SMEM);
    cudaFuncSetAttribute(flash_hmma, cudaFuncAttributeMaxDynamicSharedMemorySize, FLASH_SMEM);

    auto split = [](const float* src, __nv_bfloat16* hi, __nv_bfloat16* lo, int n) {
        int n4 = n / 4;
        split_f32<<<(n4 + 255) / 256, 256>>>((const float4*)src, (uint2*)hi, (uint2*)lo, n4);
    };

    // splits (5 launches)
    split(hs, hsH, hsL, S_LEN * HID);
    split(Wq, wqH, wqL, HID * HID);
    split(Wk, wkH, wkL, NKV * HD * HID);
    split(Wv, wvH, wvL, NKV * HD * HID);
    split(Wo, woH, woL, HID * HID);

    // fused QKV projection (V split in epilogue)
    gemm_qkv<<<dim3(48, S_LEN / 128), 256, GEMM_SMEM>>>(
        hsH, hsL, wqH, wqL, wkH, wkL, wvH, wvL, Qp, Kp, vH, vL);

    // RoPE + split (Q pre-scaled by softmax_scale * log2(e))
    const float SC = 0.08838834764831845f * 1.4426950408889634f;
    rope_split<<<(S_LEN * NH  * 32 + 255) / 256, 256>>>(Qp, cosb, sinb, qH, qL, NH,  SC);
    rope_split<<<(S_LEN * NKV * 32 + 255) / 256, 256>>>(Kp, cosb, sinb, kH, kL, NKV, 1.0f);

    // attention (writes AO split directly)
    flash_hmma<<<dim3(S_LEN / 128, NH), 256, FLASH_SMEM>>>(qH, qL, kH, kL, vH, vL, aoH, aoL);

    // output projection
    gemm_hmma<<<dim3(HID / 128, S_LEN / 128), 256, GEMM_SMEM>>>(aoH, aoL, woH, woL, out, NH * HD);
}

// round 7
// speedup vs baseline: 3.0815x; 1.0248x over previous
#include <cuda_runtime.h>
#include <cuda_bf16.h>
#include <cuda_fp16.h>
#include <math.h>
#include <cstdint>

#define S_LEN 2048
#define HID   4096
#define NH    32
#define NKV   8
#define HD    128

// ---------------- scratch (static device globals; no allocations) -----------
__device__ float g_Q [S_LEN * NH  * HD];
__device__ float g_K [S_LEN * NKV * HD];

__device__ __nv_bfloat16 g_hs_hi[S_LEN * HID],      g_hs_lo[S_LEN * HID];
__device__ __nv_bfloat16 g_wq_hi[HID * HID],        g_wq_lo[HID * HID];
__device__ __nv_bfloat16 g_wk_hi[NKV * HD * HID],   g_wk_lo[NKV * HD * HID];
__device__ __nv_bfloat16 g_wv_hi[NKV * HD * HID],   g_wv_lo[NKV * HD * HID];
__device__ __nv_bfloat16 g_wo_hi[HID * HID],        g_wo_lo[HID * HID];
__device__ __nv_bfloat16 g_ao_hi[S_LEN * HID],      g_ao_lo[S_LEN * HID];
__device__ __nv_bfloat16 g_q_hi[S_LEN * NH  * HD],  g_q_lo[S_LEN * NH  * HD];
__device__ __nv_bfloat16 g_k_hi[S_LEN * NKV * HD],  g_k_lo[S_LEN * NKV * HD];
__device__ __half        g_v_hi[S_LEN * NKV * HD],  g_v_lo[S_LEN * NKV * HD];

// ---------------- common PTX helpers ----------------------------------------
__device__ __forceinline__ uint32_t smem_u32(const void* p) {
    uint32_t a;
    asm("{ .reg .u64 t; cvta.to.shared.u64 t, %1; cvt.u32.u64 %0, t; }" : "=r"(a) : "l"(p));
    return a;
}
__device__ __forceinline__ void cp16(uint32_t dst, const void* src) {
    asm volatile("cp.async.cg.shared.global [%0], [%1], 16;" :: "r"(dst), "l"(src) : "memory");
}
#define CP_COMMIT() asm volatile("cp.async.commit_group;" ::: "memory")
template <int N> __device__ __forceinline__ void cp_wait() {
    asm volatile("cp.async.wait_group %0;" :: "n"(N) : "memory");
}
__device__ __forceinline__ void ldmx4(uint32_t* r, uint32_t addr) {
    asm volatile("ldmatrix.sync.aligned.m8n8.x4.shared.b16 {%0,%1,%2,%3}, [%4];"
                 : "=r"(r[0]), "=r"(r[1]), "=r"(r[2]), "=r"(r[3]) : "r"(addr));
}
__device__ __forceinline__ void ldmx4t(uint32_t* r, uint32_t addr) {
    asm volatile("ldmatrix.sync.aligned.m8n8.x4.trans.shared.b16 {%0,%1,%2,%3}, [%4];"
                 : "=r"(r[0]), "=r"(r[1]), "=r"(r[2]), "=r"(r[3]) : "r"(addr));
}
__device__ __forceinline__ void mma16816(float* d, const uint32_t* a, uint32_t b0, uint32_t b1) {
    asm volatile(
        "mma.sync.aligned.m16n8k16.row.col.f32.bf16.bf16.f32 "
        "{%0,%1,%2,%3}, {%4,%5,%6,%7}, {%8,%9}, {%0,%1,%2,%3};"
        : "+f"(d[0]), "+f"(d[1]), "+f"(d[2]), "+f"(d[3])
        : "r"(a[0]), "r"(a[1]), "r"(a[2]), "r"(a[3]), "r"(b0), "r"(b1));
}
__device__ __forceinline__ void mma16816h(float* d, const uint32_t* a, uint32_t b0, uint32_t b1) {
    asm volatile(
        "mma.sync.aligned.m16n8k16.row.col.f32.f16.f16.f32 "
        "{%0,%1,%2,%3}, {%4,%5,%6,%7}, {%8,%9}, {%0,%1,%2,%3};"
        : "+f"(d[0]), "+f"(d[1]), "+f"(d[2]), "+f"(d[3])
        : "r"(a[0]), "r"(a[1]), "r"(a[2]), "r"(a[3]), "r"(b0), "r"(b1));
}
__device__ __forceinline__ uint32_t pack_bf16(float a, float b) {
    return ((uint32_t)__bfloat16_as_ushort(__float2bfloat16_rn(b)) << 16) |
           __bfloat16_as_ushort(__float2bfloat16_rn(a));
}
__device__ __forceinline__ void split_pack(float a, float b, uint32_t& hp, uint32_t& lp) {
    __nv_bfloat16 ha = __float2bfloat16_rn(a), hb = __float2bfloat16_rn(b);
    hp = ((uint32_t)__bfloat16_as_ushort(hb) << 16) | __bfloat16_as_ushort(ha);
    lp = pack_bf16(a - __bfloat162float(ha), b - __bfloat162float(hb));
}
// fp16 split
__device__ __forceinline__ void split_pack_h(float a, float b, uint32_t& hp, uint32_t& lp) {
    __half ha = __float2half_rn(a), hb = __float2half_rn(b);
    hp = ((uint32_t)__half_as_ushort(hb) << 16) | __half_as_ushort(ha);
    __half la = __float2half_rn(a - __half2float(ha));
    __half lb = __float2half_rn(b - __half2float(hb));
    lp = ((uint32_t)__half_as_ushort(lb) << 16) | __half_as_ushort(la);
}
__device__ __forceinline__ float ex2f(float x) {
    float y;
    asm("ex2.approx.ftz.f32 %0, %1;" : "=f"(y) : "f"(x));
    return y;
}
// pack two fp32 into fp16x2 (lo = a, hi = b), then exp2 both halves in one MUFU op
__device__ __forceinline__ uint32_t ex2_f16x2(float a, float b) {
    uint32_t p;
    asm("cvt.rn.f16x2.f32 %0, %1, %2;" : "=r"(p) : "f"(b), "f"(a));
    asm("ex2.approx.f16x2 %0, %0;" : "+r"(p));
    return p;
}

// ---------------- split kernels ---------------------------------------------
__global__ void split_f32(const float4* __restrict__ x,
                          uint2* __restrict__ hi, uint2* __restrict__ lo, int n4) {
    int i = blockIdx.x * blockDim.x + threadIdx.x;
    if (i >= n4) return;
    float4 v = x[i];
    float xs[4] = {v.x, v.y, v.z, v.w};
    unsigned short h[4], l[4];
#pragma unroll
    for (int j = 0; j < 4; j++) {
        __nv_bfloat16 hb = __float2bfloat16_rn(xs[j]);
        float r = xs[j] - __bfloat162float(hb);
        h[j] = __bfloat16_as_ushort(hb);
        l[j] = __bfloat16_as_ushort(__float2bfloat16_rn(r));
    }
    hi[i] = make_uint2(((uint32_t)h[1] << 16) | h[0], ((uint32_t)h[3] << 16) | h[2]);
    lo[i] = make_uint2(((uint32_t)l[1] << 16) | l[0], ((uint32_t)l[3] << 16) | l[2]);
}

__global__ void rope_split(const float* __restrict__ X, const float* __restrict__ cosb,
                           const float* __restrict__ sinb,
                           __nv_bfloat16* __restrict__ hi, __nv_bfloat16* __restrict__ lo,
                           int nheads, float sc) {
    int idx = blockIdx.x * blockDim.x + threadIdx.x;
    int total = S_LEN * nheads * 32;
    if (idx >= total) return;
    int d = (idx & 31) * 2;
    int hh = (idx >> 5) % nheads;
    int s = idx / (32 * nheads);
    size_t base = (size_t)s * nheads * HD + hh * HD;
    float2 x1 = *(const float2*)(X + base + d);
    float2 x2 = *(const float2*)(X + base + d + 64);
    float2 c1 = *(const float2*)(cosb + s * HD + d);
    float2 s1 = *(const float2*)(sinb + s * HD + d);
    float2 c2 = *(const float2*)(cosb + s * HD + d + 64);
    float2 s2 = *(const float2*)(sinb + s * HD + d + 64);
    float o[4] = { (x1.x * c1.x - x2.x * s1.x) * sc, (x1.y * c1.y - x2.y * s1.y) * sc,
                   (x2.x * c2.x + x1.x * s2.x) * sc, (x2.y * c2.y + x1.y * s2.y) * sc };
    uint32_t hp0, lp0, hp1, lp1;
    split_pack(o[0], o[1], hp0, lp0);
    split_pack(o[2], o[3], hp1, lp1);
    *(uint32_t*)(hi + base + d)      = hp0;
    *(uint32_t*)(hi + base + d + 64) = hp1;
    *(uint32_t*)(lo + base + d)      = lp0;
    *(uint32_t*)(lo + base + d + 64) = lp1;
}

// =================== HMMA split-bf16 GEMM machinery ==========================
#define GBK 32
#define TILE_BYTES 8192
#define STAGE_BYTES (4 * TILE_BYTES)
#define GEMM_STAGES 3
#define GEMM_SMEM (GEMM_STAGES * STAGE_BYTES)   // 96 KB

__device__ __forceinline__ uint32_t swoff(int row, int kc) {
    return (uint32_t)(row * 64 + ((kc ^ ((row >> 1) & 3)) << 4));
}

struct GemmCore {
    uint32_t sb;
    int tid, lane, wm, wn;
    const __nv_bfloat16* gsrc[4];

    __device__ __forceinline__ void prefetch(int c, int s) {
        uint32_t sbase = sb + s * STAGE_BYTES;
#pragma unroll
        for (int t = 0; t < 4; t++) {
#pragma unroll
            for (int it = 0; it < 2; it++) {
                int u = tid + it * 256;
                int row = u >> 2, kc = u & 3;
                cp16(sbase + t * TILE_BYTES + swoff(row, kc),
                     gsrc[t] + (size_t)row * HID + c * GBK + kc * 8);
            }
        }
        CP_COMMIT();
    }

    __device__ __forceinline__ void run(float acc[4][4][4]) {
#pragma unroll
        for (int i = 0; i < 4; i++)
#pragma unroll
            for (int j = 0; j < 4; j++)
#pragma unroll
                for (int e = 0; e < 4; e++) acc[i][j][e] = 0.f;

        prefetch(0, 0);
        prefetch(1, 1);

        const int a_row = lane & 15;
        const int a_kc  = lane >> 4;
        const int b_row = (lane & 7) + ((lane >> 4) << 3);
        const int b_kc  = (lane >> 3) & 1;
        const int NC = HID / GBK;

        int s = 0;
        for (int c = 0; c < NC; c++) {
            if (c + 2 < NC) { prefetch(c + 2, (c + 2) % GEMM_STAGES); cp_wait<2>(); }
            else if (c + 1 < NC) cp_wait<1>();
            else cp_wait<0>();
            __syncthreads();

            const uint32_t stg = sb + s * STAGE_BYTES;
#pragma unroll
            for (int kk = 0; kk < 2; kk++) {
                uint32_t ah[4][4], al[4][4];
#pragma unroll
                for (int mi = 0; mi < 4; mi++) {
                    int row = wm * 64 + mi * 16 + a_row;
                    uint32_t off = swoff(row, kk * 2 + a_kc);
                    ldmx4(ah[mi], stg + 0 * TILE_BYTES + off);
                    ldmx4(al[mi], stg + 1 * TILE_BYTES + off);
                }
#pragma unroll
                for (int nf = 0; nf < 2; nf++) {
                    uint32_t bh[4], bl[4];
                    int row = wn * 32 + nf * 16 + b_row;
                    uint32_t off = swoff(row, kk * 2 + b_kc);
                    ldmx4(bh, stg + 2 * TILE_BYTES + off);
                    ldmx4(bl, stg + 3 * TILE_BYTES + off);
#pragma unroll
                    for (int mi = 0; mi < 4; mi++)
#pragma unroll
                        for (int nq = 0; nq < 2; nq++) {
                            int ni = nf * 2 + nq, p = nq * 2;
                            mma16816(acc[mi][ni], ah[mi], bh[p], bh[p + 1]);
                            mma16816(acc[mi][ni], ah[mi], bl[p], bl[p + 1]);
                            mma16816(acc[mi][ni], al[mi], bh[p], bh[p + 1]);
                        }
                }
            }
            __syncthreads();
            s = (s + 1 == GEMM_STAGES) ? 0 : s + 1;
        }
    }
};

// -------- fused QKV projection: bx<32 -> Q, 32..39 -> K, 40..47 -> V(fp16 split)
__global__ __launch_bounds__(256, 2)
void gemm_qkv(const __nv_bfloat16* __restrict__ Ahi, const __nv_bfloat16* __restrict__ Alo,
              const __nv_bfloat16* __restrict__ WqH, const __nv_bfloat16* __restrict__ WqL,
              const __nv_bfloat16* __restrict__ WkH, const __nv_bfloat16* __restrict__ WkL,
              const __nv_bfloat16* __restrict__ WvH, const __nv_bfloat16* __restrict__ WvL,
              float* __restrict__ Cq, float* __restrict__ Ck,
              __half* __restrict__ VH, __half* __restrict__ VL) {
    extern __shared__ char sm[];
    const int bx = blockIdx.x;
    const int r0 = blockIdx.y * 128;

    int part, c0;
    const __nv_bfloat16 *BH, *BL;
    if (bx < 32)      { part = 0; c0 = bx * 128;        BH = WqH; BL = WqL; }
    else if (bx < 40) { part = 1; c0 = (bx - 32) * 128; BH = WkH; BL = WkL; }
    else              { part = 2; c0 = (bx - 40) * 128; BH = WvH; BL = WvL; }

    GemmCore core;
    core.sb = smem_u32(sm);
    core.tid = threadIdx.x;
    core.lane = core.tid & 31;
    core.wm = (core.tid >> 5) >> 2;
    core.wn = (core.tid >> 5) & 3;
    core.gsrc[0] = Ahi + (size_t)r0 * HID;
    core.gsrc[1] = Alo + (size_t)r0 * HID;
    core.gsrc[2] = BH + (size_t)c0 * HID;
    core.gsrc[3] = BL + (size_t)c0 * HID;

    float acc[4][4][4];
    core.run(acc);

    const int lane = core.lane, wm = core.wm, wn = core.wn;
    if (part == 0 || part == 1) {
        float* C = (part == 0) ? Cq : Ck;
        const int N = (part == 0) ? (NH * HD) : (NKV * HD);
#pragma unroll
        for (int mi = 0; mi < 4; mi++) {
            int gr = r0 + wm * 64 + mi * 16 + (lane >> 2);
#pragma unroll
            for (int ni = 0; ni < 4; ni++) {
                int gc = c0 + wn * 32 + ni * 8 + (lane & 3) * 2;
                *(float2*)&C[(size_t)gr * N + gc]       = make_float2(acc[mi][ni][0], acc[mi][ni][1]);
                *(float2*)&C[(size_t)(gr + 8) * N + gc] = make_float2(acc[mi][ni][2], acc[mi][ni][3]);
            }
        }
    } else {
        const int N = NKV * HD;
#pragma unroll
        for (int mi = 0; mi < 4; mi++) {
            int gr = r0 + wm * 64 + mi * 16 + (lane >> 2);
#pragma unroll
            for (int ni = 0; ni < 4; ni++) {
                int gc = c0 + wn * 32 + ni * 8 + (lane & 3) * 2;
                uint32_t hp, lp;
                split_pack_h(acc[mi][ni][0], acc[mi][ni][1], hp, lp);
                *(uint32_t*)&VH[(size_t)gr * N + gc] = hp;
                *(uint32_t*)&VL[(size_t)gr * N + gc] = lp;
                split_pack_h(acc[mi][ni][2], acc[mi][ni][3], hp, lp);
                *(uint32_t*)&VH[(size_t)(gr + 8) * N + gc] = hp;
                *(uint32_t*)&VL[(size_t)(gr + 8) * N + gc] = lp;
            }
        }
    }
}

// -------- generic GEMM (used for O projection) -------------------------------
__global__ __launch_bounds__(256, 2)
void gemm_hmma(const __nv_bfloat16* __restrict__ Ahi, const __nv_bfloat16* __restrict__ Alo,
               const __nv_bfloat16* __restrict__ Bhi, const __nv_bfloat16* __restrict__ Blo,
               float* __restrict__ C, int N) {
    extern __shared__ char sm[];
    const int r0 = blockIdx.y * 128;
    const int c0 = blockIdx.x * 128;

    GemmCore core;
    core.sb = smem_u32(sm);
    core.tid = threadIdx.x;
    core.lane = core.tid & 31;
    core.wm = (core.tid >> 5) >> 2;
    core.wn = (core.tid >> 5) & 3;
    core.gsrc[0] = Ahi + (size_t)r0 * HID;
    core.gsrc[1] = Alo + (size_t)r0 * HID;
    core.gsrc[2] = Bhi + (size_t)c0 * HID;
    core.gsrc[3] = Blo + (size_t)c0 * HID;

    float acc[4][4][4];
    core.run(acc);

    const int lane = core.lane, wm = core.wm, wn = core.wn;
#pragma unroll
    for (int mi = 0; mi < 4; mi++) {
        int gr = r0 + wm * 64 + mi * 16 + (lane >> 2);
#pragma unroll
        for (int ni = 0; ni < 4; ni++) {
            int gc = c0 + wn * 32 + ni * 8 + (lane & 3) * 2;
            *(float2*)&C[(size_t)gr * N + gc]       = make_float2(acc[mi][ni][0], acc[mi][ni][1]);
            *(float2*)&C[(size_t)(gr + 8) * N + gc] = make_float2(acc[mi][ni][2], acc[mi][ni][3]);
        }
    }
}

// =================== Flash attention: bf16x3 QK, fp16 softmax/PV ============
#define FS_QH 0
#define FS_QL 32768
#define FS_KV 65536
#define FS_STAGE 65536
#define FLASH_SMEM (FS_KV + 2 * FS_STAGE)   // 196608

__device__ __forceinline__ uint32_t fladdr(uint32_t base, int rb, int cb,
                                           int l7, int selr, int selc) {
    int r = rb + l7 + selr;
    int c = cb + selc;
    return base + r * 256 + (((c ^ (r & 7)) & 15) << 4);
}

__global__ __launch_bounds__(256, 1)
void flash_hmma(const __nv_bfloat16* __restrict__ Qhi, const __nv_bfloat16* __restrict__ Qlo,
                const __nv_bfloat16* __restrict__ Khi, const __nv_bfloat16* __restrict__ Klo,
                const __half* __restrict__ Vhi, const __half* __restrict__ Vlo,
                __nv_bfloat16* __restrict__ AOhi, __nv_bfloat16* __restrict__ AOlo) {
    extern __shared__ char fsm[];
    const uint32_t sb = smem_u32(fsm);
    const int tid = threadIdx.x;
    const int lane = tid & 31, wm = tid >> 5;
    const int gid = lane >> 2, tig = lane & 3;
    const int l7 = lane & 7, selr = ((lane >> 3) & 1) << 3, selc = lane >> 4;

    const int qb = (int)(gridDim.x - 1 - blockIdx.x);
    const int h = blockIdx.y;
    const int kv = h >> 2;
    const int q0 = qb * 128;
    const int njb = 2 * (qb + 1);

#pragma unroll
    for (int i = 0; i < 8; i++) {
        int u = tid + i * 256;
        int row = u >> 4, c = u & 15;
        uint32_t so = (row << 8) + (((c ^ (row & 7))) << 4);
        const size_t gi = (size_t)(q0 + row) * (NH * HD) + h * HD + c * 8;
        cp16(sb + FS_QH + so, Qhi + gi);
        cp16(sb + FS_QL + so, Qlo + gi);
    }
    const void* kvsrc[4] = {Khi, Klo, Vhi, Vlo};
    auto prefetch_kv = [&](int jb, int s) {
        uint32_t sbase = sb + FS_KV + s * FS_STAGE;
#pragma unroll
        for (int t = 0; t < 4; t++) {
#pragma unroll
            for (int i = 0; i < 4; i++) {
                int u = tid + i * 256;
                int row = u >> 4, c = u & 15;
                uint32_t so = (row << 8) + (((c ^ (row & 7))) << 4);
                cp16(sbase + t * 16384 + so,
                     (const char*)kvsrc[t] + ((size_t)(jb * 64 + row) * (NKV * HD) + kv * HD + c * 8) * 2);
            }
        }
        CP_COMMIT();
    };
    prefetch_kv(0, 0);

    float oacc[16][4];
#pragma unroll
    for (int j = 0; j < 16; j++)
#pragma unroll
        for (int e = 0; e < 4; e++) oacc[j][e] = 0.f;
    float m0 = -1e30f, m1 = -1e30f, l0 = 0.f, l1 = 0.f;

    const int wrow0 = q0 + wm * 16;

    for (int jb = 0; jb < njb; jb++) {
        if (jb + 1 < njb) { prefetch_kv(jb + 1, (jb + 1) & 1); cp_wait<1>(); }
        else cp_wait<0>();
        __syncthreads();

        const int k0 = jb * 64;
        const bool skip = (k0 > wrow0 + 15);
        if (!skip) {
            const uint32_t stg = sb + FS_KV + (jb & 1) * FS_STAGE;
            float sacc[8][4];
#pragma unroll
            for (int j = 0; j < 8; j++)
#pragma unroll
                for (int e = 0; e < 4; e++) sacc[j][e] = 0.f;
#pragma unroll
            for (int ks = 0; ks < 8; ks++) {
                uint32_t ah[4], al[4];
                uint32_t aa = fladdr(sb + FS_QH, wm * 16, 2 * ks, l7, selr, selc);
                ldmx4(ah, aa);
                ldmx4(al, aa + (FS_QL - FS_QH));
#pragma unroll
                for (int g4 = 0; g4 < 4; g4++) {
                    uint32_t bh[4], bl[4];
                    uint32_t ba = fladdr(stg, 16 * g4, 2 * ks, l7, selr, selc);
                    ldmx4(bh, ba);
                    ldmx4(bl, ba + 16384);
                    mma16816(sacc[2 * g4],     ah, bh[0], bh[2]);
                    mma16816(sacc[2 * g4],     ah, bl[0], bl[2]);
                    mma16816(sacc[2 * g4],     al, bh[0], bh[2]);
                    mma16816(sacc[2 * g4 + 1], ah, bh[1], bh[3]);
                    mma16816(sacc[2 * g4 + 1], ah, bl[1], bl[3]);
                    mma16816(sacc[2 * g4 + 1], al, bh[1], bh[3]);
                }
            }
            if (k0 + 63 > wrow0) {
                int row0 = wrow0 + gid;
#pragma unroll
                for (int j = 0; j < 8; j++) {
                    int col = k0 + 8 * j + 2 * tig;
                    if (col > row0)         sacc[j][0] = -1e30f;
                    if (col + 1 > row0)     sacc[j][1] = -1e30f;
                    if (col > row0 + 8)     sacc[j][2] = -1e30f;
                    if (col + 1 > row0 + 8) sacc[j][3] = -1e30f;
                }
            }
            float tm0 = -1e30f, tm1 = -1e30f;
#pragma unroll
            for (int j = 0; j < 8; j++) {
                tm0 = fmaxf(tm0, fmaxf(sacc[j][0], sacc[j][1]));
                tm1 = fmaxf(tm1, fmaxf(sacc[j][2], sacc[j][3]));
            }
            tm0 = fmaxf(tm0, __shfl_xor_sync(0xffffffffu, tm0, 1));
            tm0 = fmaxf(tm0, __shfl_xor_sync(0xffffffffu, tm0, 2));
            tm1 = fmaxf(tm1, __shfl_xor_sync(0xffffffffu, tm1, 1));
            tm1 = fmaxf(tm1, __shfl_xor_sync(0xffffffffu, tm1, 2));
            float mn0 = fmaxf(m0, tm0), mn1 = fmaxf(m1, tm1);
            float a0 = ex2f(m0 - mn0), a1 = ex2f(m1 - mn1);
            m0 = mn0; m1 = mn1;

            // fp16x2 exp: one MUFU per pair; p stays packed fp16 for the PV MMA
            uint32_t pp[8][2];
            float rs0 = 0.f, rs1 = 0.f;
#pragma unroll
            for (int j = 0; j < 8; j++) {
                pp[j][0] = ex2_f16x2(sacc[j][0] - mn0, sacc[j][1] - mn0);
                pp[j][1] = ex2_f16x2(sacc[j][2] - mn1, sacc[j][3] - mn1);
                float2 f0 = __half22float2(*reinterpret_cast<__half2*>(&pp[j][0]));
                float2 f1 = __half22float2(*reinterpret_cast<__half2*>(&pp[j][1]));
                rs0 += f0.x + f0.y;
                rs1 += f1.x + f1.y;
            }
            rs0 += __shfl_xor_sync(0xffffffffu, rs0, 1);
            rs0 += __shfl_xor_sync(0xffffffffu, rs0, 2);
            rs1 += __shfl_xor_sync(0xffffffffu, rs1, 1);
            rs1 += __shfl_xor_sync(0xffffffffu, rs1, 2);
            l0 = l0 * a0 + rs0;
            l1 = l1 * a1 + rs1;
#pragma unroll
            for (int j = 0; j < 16; j++) {
                oacc[j][0] *= a0; oacc[j][1] *= a0;
                oacc[j][2] *= a1; oacc[j][3] *= a1;
            }
            // ---- O += P V : P fp16, V fp16 hi/lo (4 MMAs per fragment) ----
#pragma unroll
            for (int ks = 0; ks < 4; ks++) {
                uint32_t pf[4] = { pp[2*ks][0], pp[2*ks][1], pp[2*ks+1][0], pp[2*ks+1][1] };
#pragma unroll
                for (int g = 0; g < 8; g++) {
                    uint32_t vh[4], vl[4];
                    uint32_t va = fladdr(stg + 32768, 16 * ks, 2 * g, l7, selr, selc);
                    ldmx4t(vh, va);
                    ldmx4t(vl, va + 16384);
                    mma16816h(oacc[2 * g],     pf, vh[0], vh[1]);
                    mma16816h(oacc[2 * g],     pf, vl[0], vl[1]);
                    mma16816h(oacc[2 * g + 1], pf, vh[2], vh[3]);
                    mma16816h(oacc[2 * g + 1], pf, vl[2], vl[3]);
                }
            }
        }
        __syncthreads();
    }

    // ---- normalize + split-write bf16 hi/lo ----
    const float inv0 = 1.f / l0, inv1 = 1.f / l1;
    const int row0 = wrow0 + gid;
#pragma unroll
    for (int j = 0; j < 16; j++) {
        size_t d = (size_t)h * HD + 8 * j + 2 * tig;
        uint32_t hp, lp;
        split_pack(oacc[j][0] * inv0, oacc[j][1] * inv0, hp, lp);
        *(uint32_t*)&AOhi[(size_t)row0 * (NH * HD) + d] = hp;
        *(uint32_t*)&AOlo[(size_t)row0 * (NH * HD) + d] = lp;
        split_pack(oacc[j][2] * inv1, oacc[j][3] * inv1, hp, lp);
        *(uint32_t*)&AOhi[(size_t)(row0 + 8) * (NH * HD) + d] = hp;
        *(uint32_t*)&AOlo[(size_t)(row0 + 8) * (NH * HD) + d] = lp;
    }
}

// ---------------- launch ----------------------------------------------------
extern "C" void kernel_launch(void* const* d_in, const int* in_sizes, int n_in,
                              void* d_out, int out_size) {
    const float* hs   = (const float*)d_in[0];
    const float* cosb = (const float*)d_in[1];
    const float* sinb = (const float*)d_in[2];
    const float* Wq   = (const float*)d_in[4];
    const float* Wk   = (const float*)d_in[5];
    const float* Wv   = (const float*)d_in[6];
    const float* Wo   = (const float*)d_in[7];
    float* out = (float*)d_out;

    float *Qp, *Kp;
    cudaGetSymbolAddress((void**)&Qp,  g_Q);
    cudaGetSymbolAddress((void**)&Kp,  g_K);
    __nv_bfloat16 *hsH, *hsL, *wqH, *wqL, *wkH, *wkL, *wvH, *wvL, *woH, *woL, *aoH, *aoL;
    __nv_bfloat16 *qH, *qL, *kH, *kL;
    __half *vH, *vL;
    cudaGetSymbolAddress((void**)&hsH, g_hs_hi); cudaGetSymbolAddress((void**)&hsL, g_hs_lo);
    cudaGetSymbolAddress((void**)&wqH, g_wq_hi); cudaGetSymbolAddress((void**)&wqL, g_wq_lo);
    cudaGetSymbolAddress((void**)&wkH, g_wk_hi); cudaGetSymbolAddress((void**)&wkL, g_wk_lo);
    cudaGetSymbolAddress((void**)&wvH, g_wv_hi); cudaGetSymbolAddress((void**)&wvL, g_wv_lo);
    cudaGetSymbolAddress((void**)&woH, g_wo_hi); cudaGetSymbolAddress((void**)&woL, g_wo_lo);
    cudaGetSymbolAddress((void**)&aoH, g_ao_hi); cudaGetSymbolAddress((void**)&aoL, g_ao_lo);
    cudaGetSymbolAddress((void**)&qH,  g_q_hi);  cudaGetSymbolAddress((void**)&qL,  g_q_lo);
    cudaGetSymbolAddress((void**)&kH,  g_k_hi);  cudaGetSymbolAddress((void**)&kL,  g_k_lo);
    cudaGetSymbolAddress((void**)&vH,  g_v_hi);  cudaGetSymbolAddress((void**)&vL,  g_v_lo);

    cudaFuncSetAttribute(gemm_qkv,  cudaFuncAttributeMaxDynamicSharedMemorySize, GEMM_SMEM);
    cudaFuncSetAttribute(gemm_hmma, cudaFuncAttributeMaxDynamicSharedMemorySize, GEMM_SMEM);
    cudaFuncSetAttribute(flash_hmma, cudaFuncAttributeMaxDynamicSharedMemorySize, FLASH_SMEM);

    auto split = [](const float* src, __nv_bfloat16* hi, __nv_bfloat16* lo, int n) {
        int n4 = n / 4;
        split_f32<<<(n4 + 255) / 256, 256>>>((const float4*)src, (uint2*)hi, (uint2*)lo, n4);
    };

    // splits
    split(hs, hsH, hsL, S_LEN * HID);
    split(Wq, wqH, wqL, HID * HID);
    split(Wk, wkH, wkL, NKV * HD * HID);
    split(Wv, wvH, wvL, NKV * HD * HID);
    split(Wo, woH, woL, HID * HID);

    // fused QKV projection (V fp16-split in epilogue)
    gemm_qkv<<<dim3(48, S_LEN / 128), 256, GEMM_SMEM>>>(
        hsH, hsL, wqH, wqL, wkH, wkL, wvH, wvL, Qp, Kp, vH, vL);

    // RoPE + split (Q pre-scaled by softmax_scale * log2(e))
    const float SC = 0.08838834764831845f * 1.4426950408889634f;
    rope_split<<<(S_LEN * NH  * 32 + 255) / 256, 256>>>(Qp, cosb, sinb, qH, qL, NH,  SC);
    rope_split<<<(S_LEN * NKV * 32 + 255) / 256, 256>>>(Kp, cosb, sinb, kH, kL, NKV, 1.0f);

    // attention
    flash_hmma<<<dim3(S_LEN / 128, NH), 256, FLASH_SMEM>>>(qH, qL, kH, kL, vH, vL, aoH, aoL);

    // output projection
    gemm_hmma<<<dim3(HID / 128, S_LEN / 128), 256, GEMM_SMEM>>>(aoH, aoL, woH, woL, out, NH * HD);
}